// round 2
// baseline (speedup 1.0000x reference)
#include <cuda_runtime.h>
#include <math.h>

#ifndef M_PI
#define M_PI 3.14159265358979323846
#endif

#define BATCH 128
#define HH    256
#define CC    10
#define MATSZ (HH*HH)          /* 65536 */
#define DEG   22
#define NSTEPS (DEG-1)         /* 21 recurrence steps: T2..T22 */

// ---------------- scratch (static device globals; no runtime allocation) ----
__device__ float g_Y [BATCH*MATSZ];   // Chebyshev argument Y_b
__device__ float g_Ta[BATCH*MATSZ];   // T_{k-1} / rotating buffer
__device__ float g_Tb[BATCH*MATSZ];   // T_k     / rotating buffer
__device__ float g_F [BATCH*MATSZ];   // accumulated log(X_b)
__device__ float g_Ws[CC*MATSZ];      // symmetrized W
__device__ float g_center[MATSZ];
__device__ float g_P [CC*MATSZ];
__device__ float g_acc;

struct ChebArgs { float c[NSTEPS]; };

// ---------------- prep: Y = s*X + o*I ; Ta = I ; Tb = Y ; F = c0*I + c1*Y ----
__global__ void prep_mats(const float* __restrict__ X,
                          float c0, float c1, float s, float o) {
    unsigned gid = blockIdx.x * blockDim.x + threadIdx.x;   // float4 index
    float4 x = ((const float4*)X)[gid];
    unsigned within = gid & (MATSZ/4 - 1);
    int i  = (int)(within >> 6);
    int j0 = (int)(within & 63) << 2;

    float id0 = (i == j0+0) ? 1.f : 0.f;
    float id1 = (i == j0+1) ? 1.f : 0.f;
    float id2 = (i == j0+2) ? 1.f : 0.f;
    float id3 = (i == j0+3) ? 1.f : 0.f;

    float4 yv;
    yv.x = s*x.x + o*id0;  yv.y = s*x.y + o*id1;
    yv.z = s*x.z + o*id2;  yv.w = s*x.w + o*id3;

    float4 iv = make_float4(id0, id1, id2, id3);
    float4 fv;
    fv.x = c0*id0 + c1*yv.x;  fv.y = c0*id1 + c1*yv.y;
    fv.z = c0*id2 + c1*yv.z;  fv.w = c0*id3 + c1*yv.w;

    ((float4*)g_Y )[gid] = yv;
    ((float4*)g_Tb)[gid] = yv;
    ((float4*)g_Ta)[gid] = iv;
    ((float4*)g_F )[gid] = fv;
    if (gid == 0) g_acc = 0.f;
}

// ---------------- Ws = 0.5*(W + W^T) per class ------------------------------
__global__ void prep_W(const float* __restrict__ W) {
    int gid = blockIdx.x * blockDim.x + threadIdx.x;        // 0 .. CC*MATSZ-1
    int c   = gid >> 16;
    int rem = gid & 65535;
    int i   = rem >> 8, j = rem & 255;
    g_Ws[gid] = 0.5f * (W[gid] + W[(c<<16) + (j<<8) + i]);
}

// ---------------- Chebyshev recurrence: one CTA per matrix ------------------
// step: Tnext = 2*Y*Tcur - Tprev (written in-place into Tprev buffer),
//       F += c_k * Tnext, then swap(Tprev, Tcur).
__global__ void __launch_bounds__(256) cheb_kernel(ChebArgs args) {
    const int b = blockIdx.x;
    const float* __restrict__ Y = g_Y + (size_t)b * MATSZ;
    float* Tprev = g_Ta + (size_t)b * MATSZ;
    float* Tcur  = g_Tb + (size_t)b * MATSZ;
    float* __restrict__ F = g_F + (size_t)b * MATSZ;

    __shared__ float As[128][32];   // A tile:  rows x k   (row-major)
    __shared__ float Bs[32][128];   // B tile:  k x cols

    const int tid = threadIdx.x;
    const int tx  = tid & 15;       // 0..15 -> 8 output cols each
    const int ty  = tid >> 4;       // 0..15 -> 8 output rows each

    #pragma unroll 1
    for (int step = 0; step < NSTEPS; ++step) {
        const float ck = args.c[step];
        #pragma unroll 1
        for (int ot = 0; ot < 4; ++ot) {
            const int row0 = (ot >> 1) << 7;
            const int col0 = (ot & 1) << 7;

            float acc[8][8];
            #pragma unroll
            for (int ii = 0; ii < 8; ++ii)
                #pragma unroll
                for (int jj = 0; jj < 8; ++jj) acc[ii][jj] = 0.f;

            #pragma unroll 1
            for (int kt = 0; kt < 256; kt += 32) {
                // load A tile (Y rows row0..row0+127, cols kt..kt+31)
                #pragma unroll
                for (int l = 0; l < 4; ++l) {
                    int t  = tid + (l << 8);        // 0..1023 (float4 units)
                    int ai = t >> 3;                // 0..127
                    int ak = (t & 7) << 2;          // 0,4,..,28
                    *(float4*)&As[ai][ak] =
                        *(const float4*)&Y[(size_t)(row0+ai)*256 + kt + ak];
                }
                // load B tile (Tcur rows kt..kt+31, cols col0..col0+127)
                #pragma unroll
                for (int l = 0; l < 4; ++l) {
                    int t  = tid + (l << 8);
                    int bk = t >> 5;                // 0..31
                    int bj = (t & 31) << 2;         // 0,4,..,124
                    *(float4*)&Bs[bk][bj] =
                        *(const float4*)&Tcur[(size_t)(kt+bk)*256 + col0 + bj];
                }
                __syncthreads();
                #pragma unroll 8
                for (int kk = 0; kk < 32; ++kk) {
                    float af[8], bf[8];
                    #pragma unroll
                    for (int u = 0; u < 8; ++u) af[u] = As[ty*8+u][kk];
                    #pragma unroll
                    for (int u = 0; u < 8; ++u) bf[u] = Bs[kk][tx*8+u];
                    #pragma unroll
                    for (int ii = 0; ii < 8; ++ii)
                        #pragma unroll
                        for (int jj = 0; jj < 8; ++jj)
                            acc[ii][jj] += af[ii] * bf[jj];
                }
                __syncthreads();
            }
            // fused epilogue: Tnext = 2*acc - Tprev (in place), F += ck*Tnext
            #pragma unroll
            for (int ii = 0; ii < 8; ++ii) {
                int r = row0 + ty*8 + ii;
                size_t base = (size_t)r*256 + col0 + tx*8;
                float4 tp0 = *(float4*)&Tprev[base];
                float4 tp1 = *(float4*)&Tprev[base+4];
                float4 f0  = *(float4*)&F[base];
                float4 f1  = *(float4*)&F[base+4];
                float4 o0, o1;
                o0.x = 2.f*acc[ii][0] - tp0.x;  o0.y = 2.f*acc[ii][1] - tp0.y;
                o0.z = 2.f*acc[ii][2] - tp0.z;  o0.w = 2.f*acc[ii][3] - tp0.w;
                o1.x = 2.f*acc[ii][4] - tp1.x;  o1.y = 2.f*acc[ii][5] - tp1.y;
                o1.z = 2.f*acc[ii][6] - tp1.z;  o1.w = 2.f*acc[ii][7] - tp1.w;
                f0.x += ck*o0.x;  f0.y += ck*o0.y;  f0.z += ck*o0.z;  f0.w += ck*o0.w;
                f1.x += ck*o1.x;  f1.y += ck*o1.y;  f1.z += ck*o1.z;  f1.w += ck*o1.w;
                *(float4*)&Tprev[base]   = o0;
                *(float4*)&Tprev[base+4] = o1;
                *(float4*)&F[base]       = f0;
                *(float4*)&F[base+4]     = f1;
            }
        }
        float* tmp = Tprev; Tprev = Tcur; Tcur = tmp;
        __syncthreads();   // block-scope fence: epilogue writes visible next step
    }
}

// ---------------- center = mean_b F_b ---------------------------------------
__global__ void center_kernel() {
    int t = blockIdx.x * blockDim.x + threadIdx.x;   // float4 idx 0..16383
    float4 s = make_float4(0.f, 0.f, 0.f, 0.f);
    for (int b = 0; b < BATCH; ++b) {
        float4 v = ((const float4*)(g_F + (size_t)b*MATSZ))[t];
        s.x += v.x; s.y += v.y; s.z += v.z; s.w += v.w;
    }
    const float inv = 1.f / BATCH;
    s.x *= inv; s.y *= inv; s.z *= inv; s.w *= inv;
    ((float4*)g_center)[t] = s;
}

// ---------------- output[b,c] = <Ws_c, F_b> (Frobenius) ---------------------
__global__ void out_kernel(float* __restrict__ out) {
    int c = blockIdx.x, b = blockIdx.y;
    const float4* F4 = (const float4*)(g_F  + (size_t)b*MATSZ);
    const float4* W4 = (const float4*)(g_Ws + (size_t)c*MATSZ);
    float acc = 0.f;
    for (int t = threadIdx.x; t < MATSZ/4; t += 256) {
        float4 f = F4[t], w = W4[t];
        acc += f.x*w.x + f.y*w.y + f.z*w.z + f.w*w.w;
    }
    __shared__ float red[8];
    #pragma unroll
    for (int o = 16; o; o >>= 1) acc += __shfl_down_sync(0xffffffffu, acc, o);
    if ((threadIdx.x & 31) == 0) red[threadIdx.x >> 5] = acc;
    __syncthreads();
    if (threadIdx.x < 8) {
        float v = red[threadIdx.x];
        #pragma unroll
        for (int o = 4; o; o >>= 1) v += __shfl_down_sync(0xffu, v, o);
        if (threadIdx.x == 0) out[b*CC + c] = v;
    }
}

// ---------------- P_c = Ws_c @ center ---------------------------------------
__global__ void p_kernel() {
    int c  = blockIdx.y;
    int r0 = blockIdx.x * 32;
    __shared__ float Wb[32][256];
    for (int l = 0; l < 32; ++l)
        Wb[l][threadIdx.x] = g_Ws[(size_t)c*MATSZ + (size_t)(r0+l)*256 + threadIdx.x];
    __syncthreads();
    int j = threadIdx.x;
    float acc[32];
    #pragma unroll
    for (int ii = 0; ii < 32; ++ii) acc[ii] = 0.f;
    for (int k = 0; k < 256; ++k) {
        float bv = g_center[k*256 + j];
        #pragma unroll
        for (int ii = 0; ii < 32; ++ii) acc[ii] += Wb[ii][k] * bv;
    }
    for (int ii = 0; ii < 32; ++ii)
        g_P[(size_t)c*MATSZ + (size_t)(r0+ii)*256 + j] = acc[ii];
}

// ---------------- g partials: sum_ij P[c,i,j]*P[c,j,i] ----------------------
__global__ void g_kernel() {
    int c = blockIdx.x;
    const float* P = g_P + (size_t)c*MATSZ;
    float acc = 0.f;
    for (int idx = threadIdx.x; idx < MATSZ; idx += 256) {
        int i = idx >> 8, j = idx & 255;
        acc += P[idx] * P[j*256 + i];
    }
    __shared__ float red[8];
    #pragma unroll
    for (int o = 16; o; o >>= 1) acc += __shfl_down_sync(0xffffffffu, acc, o);
    if ((threadIdx.x & 31) == 0) red[threadIdx.x >> 5] = acc;
    __syncthreads();
    if (threadIdx.x < 8) {
        float v = red[threadIdx.x];
        #pragma unroll
        for (int o = 4; o; o >>= 1) v += __shfl_down_sync(0xffu, v, o);
        if (threadIdx.x == 0) atomicAdd(&g_acc, v);
    }
}

__global__ void fin_kernel(float* __restrict__ out, int out_size) {
    out[out_size - 1] = g_acc * (1.f / CC);
}

// ---------------- host ------------------------------------------------------
extern "C" void kernel_launch(void* const* d_in, const int* in_sizes, int n_in,
                              void* d_out, int out_size) {
    const float* X = (const float*)d_in[0];   // mat_feats [128,256,256]
    const float* W = (const float*)d_in[1];   // W         [10,256,256]
    float* out = (float*)d_out;

    // Chebyshev coefficients of log(x) on [a,b] (computed at capture time)
    const double a = 0.9, bb = 6.0;
    double coef[DEG+1];
    {
        const int N = 128;
        for (int k = 0; k <= DEG; ++k) {
            double s = 0.0;
            for (int j = 0; j < N; ++j) {
                double th  = M_PI * (j + 0.5) / N;
                double lam = 0.5*(bb+a) + 0.5*(bb-a)*cos(th);
                s += log(lam) * cos(k*th);
            }
            coef[k] = 2.0 / N * s;
        }
        coef[0] *= 0.5;
    }
    const float sc = (float)( 2.0/(bb-a));
    const float of = (float)(-(bb+a)/(bb-a));
    ChebArgs ca;
    for (int k = 0; k < NSTEPS; ++k) ca.c[k] = (float)coef[k+2];

    prep_mats<<<(BATCH*MATSZ/4)/256, 256>>>(X, (float)coef[0], (float)coef[1], sc, of);
    prep_W<<<(CC*MATSZ)/256, 256>>>(W);
    cheb_kernel<<<BATCH, 256>>>(ca);
    center_kernel<<<(MATSZ/4)/256, 256>>>();
    out_kernel<<<dim3(CC, BATCH), 256>>>(out);
    p_kernel<<<dim3(8, CC), 256>>>();
    g_kernel<<<CC, 256>>>();
    fin_kernel<<<1, 1>>>(out, out_size);
}

// round 5
// speedup vs baseline: 1.5191x; 1.5191x over previous
#include <cuda_runtime.h>
#include <cuda_bf16.h>
#include <math.h>
#include <stdint.h>

#ifndef M_PI
#define M_PI 3.14159265358979323846
#endif

#define BATCH 128
#define HH    256
#define CC    10
#define MATSZ (HH*HH)
#define DEG   22
#define NSTEPS (DEG-1)

#define PADK   40                 /* smem row stride in bf16 elements (80 B) */
#define A_OFF  0u
#define AL_OFF 10240u             /* 128*80 */
#define B_OFF  20480u
#define BL_OFF 40960u
#define STAGE  61440u             /* 20480 + 2*20480 */

// ---------------- scratch ----------------------------------------------------
__device__ __align__(16) __nv_bfloat16 g_Yh[BATCH*MATSZ];
__device__ __align__(16) __nv_bfloat16 g_Yl[BATCH*MATSZ];
__device__ __align__(16) __nv_bfloat16 g_S0h[BATCH*MATSZ];
__device__ __align__(16) __nv_bfloat16 g_S0l[BATCH*MATSZ];
__device__ __align__(16) __nv_bfloat16 g_S1h[BATCH*MATSZ];
__device__ __align__(16) __nv_bfloat16 g_S1l[BATCH*MATSZ];
__device__ float g_F [BATCH*MATSZ];
__device__ float g_Ws[CC*MATSZ];
__device__ float g_center[MATSZ];
__device__ float g_P [CC*MATSZ];
__device__ float g_acc;

struct ChebArgs { float c[NSTEPS]; };

// ---------------- PTX helpers ------------------------------------------------
__device__ __forceinline__ uint32_t smem_u32(const void* p) {
    uint32_t a;
    asm("{ .reg .u64 t; cvta.to.shared.u64 t, %1; cvt.u32.u64 %0, t; }"
        : "=r"(a) : "l"(p));
    return a;
}
__device__ __forceinline__ void cpasync16(uint32_t dst, const void* src) {
    asm volatile("cp.async.cg.shared.global [%0], [%1], 16;"
                 :: "r"(dst), "l"(src) : "memory");
}
__device__ __forceinline__ void cp_commit() {
    asm volatile("cp.async.commit_group;" ::: "memory");
}
template<int N> __device__ __forceinline__ void cp_wait() {
    asm volatile("cp.async.wait_group %0;" :: "n"(N) : "memory");
}
__device__ __forceinline__ void ldsm4(uint32_t& r0, uint32_t& r1,
                                      uint32_t& r2, uint32_t& r3, uint32_t a) {
    asm volatile("ldmatrix.sync.aligned.m8n8.x4.shared.b16 {%0,%1,%2,%3}, [%4];"
                 : "=r"(r0), "=r"(r1), "=r"(r2), "=r"(r3) : "r"(a));
}
__device__ __forceinline__ void mma16816(float* c, const uint32_t* a,
                                         uint32_t b0, uint32_t b1) {
    asm volatile(
        "mma.sync.aligned.m16n8k16.row.col.f32.bf16.bf16.f32 "
        "{%0,%1,%2,%3}, {%4,%5,%6,%7}, {%8,%9}, {%0,%1,%2,%3};"
        : "+f"(c[0]), "+f"(c[1]), "+f"(c[2]), "+f"(c[3])
        : "r"(a[0]), "r"(a[1]), "r"(a[2]), "r"(a[3]), "r"(b0), "r"(b1));
}

// ---------------- prep: Y = s*X + o*I ; split bf16 hi/lo; init slots, F -----
__global__ void prep_mats(const float* __restrict__ X,
                          float c0, float c1, float s, float o) {
    unsigned gid = blockIdx.x * blockDim.x + threadIdx.x;
    float4 x = ((const float4*)X)[gid];
    unsigned within = gid & (MATSZ/4 - 1);
    int i  = (int)(within >> 6);
    int j0 = (int)(within & 63) << 2;

    float id[4], y[4];
    id[0] = (i == j0+0) ? 1.f : 0.f;  id[1] = (i == j0+1) ? 1.f : 0.f;
    id[2] = (i == j0+2) ? 1.f : 0.f;  id[3] = (i == j0+3) ? 1.f : 0.f;
    y[0] = s*x.x + o*id[0];  y[1] = s*x.y + o*id[1];
    y[2] = s*x.z + o*id[2];  y[3] = s*x.w + o*id[3];

    float4 fv;
    fv.x = c0*id[0] + c1*y[0];  fv.y = c0*id[1] + c1*y[1];
    fv.z = c0*id[2] + c1*y[2];  fv.w = c0*id[3] + c1*y[3];
    ((float4*)g_F)[gid] = fv;

    unsigned hh[4], ll[4];
    #pragma unroll
    for (int q = 0; q < 4; ++q) {
        __nv_bfloat16 h = __float2bfloat16(y[q]);
        float hf = __bfloat162float(h);
        __nv_bfloat16 l = __float2bfloat16(y[q] - hf);
        hh[q] = __bfloat16_as_ushort(h);
        ll[q] = __bfloat16_as_ushort(l);
    }
    uint2 ph = make_uint2(hh[0] | (hh[1]<<16), hh[2] | (hh[3]<<16));
    uint2 pl = make_uint2(ll[0] | (ll[1]<<16), ll[2] | (ll[3]<<16));
    ((uint2*)g_Yh)[gid]  = ph;  ((uint2*)g_Yl)[gid]  = pl;
    ((uint2*)g_S1h)[gid] = ph;  ((uint2*)g_S1l)[gid] = pl;

    const unsigned one = 0x3F80u;
    uint2 pi = make_uint2(((i==j0+0)?one:0u) | (((i==j0+1)?one:0u)<<16),
                          ((i==j0+2)?one:0u) | (((i==j0+3)?one:0u)<<16));
    ((uint2*)g_S0h)[gid] = pi;
    ((uint2*)g_S0l)[gid] = make_uint2(0u, 0u);
    if (gid == 0) g_acc = 0.f;
}

__global__ void prep_W(const float* __restrict__ W) {
    int gid = blockIdx.x * blockDim.x + threadIdx.x;
    int c   = gid >> 16;
    int rem = gid & 65535;
    int i   = rem >> 8, j = rem & 255;
    g_Ws[gid] = 0.5f * (W[gid] + W[(c<<16) + (j<<8) + i]);
}

// ---------------- HMMA Chebyshev recurrence ---------------------------------
__global__ void __launch_bounds__(256, 1) cheb_mma(ChebArgs args) {
    extern __shared__ char dsm[];
    const uint32_t sb = smem_u32(dsm);

    const int b    = blockIdx.x;
    const int tid  = threadIdx.x;
    const int wid  = tid >> 5;
    const int lane = tid & 31;
    const int wm0  = (wid >> 2) << 6;      // 0 / 64 within 128-row half
    const int wn0  = (wid & 3)  << 6;      // 0,64,128,192
    const int laneA  = lane & 15;
    const int laneHi = (lane >> 4) << 4;   // 0 or 16 bytes

    const size_t moff = (size_t)b * MATSZ;
    const __nv_bfloat16* Yh = g_Yh + moff;
    const __nv_bfloat16* Yl = g_Yl + moff;
    float* Fm = g_F + moff;

    // per-lane smem bases for ldmatrix (A: row wm0+laneA; B: row wn0+np*16+laneA)
    const uint32_t aA0 = sb + (uint32_t)((wm0 + laneA) * 80) + (uint32_t)laneHi;
    const uint32_t aB0 = sb + B_OFF + (uint32_t)((wn0 + laneA) * 80) + (uint32_t)laneHi;

    #pragma unroll 1
    for (int step = 0; step < NSTEPS; ++step) {
        const float ck = args.c[step];
        const __nv_bfloat16 *curh, *curl;
        __nv_bfloat16 *dsth, *dstl;
        if ((step & 1) == 0) { curh = g_S1h+moff; curl = g_S1l+moff;
                               dsth = g_S0h+moff; dstl = g_S0l+moff; }
        else                 { curh = g_S0h+moff; curl = g_S0l+moff;
                               dsth = g_S1h+moff; dstl = g_S1l+moff; }

        #pragma unroll 1
        for (int half = 0; half < 2; ++half) {
            const int m0 = half << 7;

            float acc[4][8][4];
            #pragma unroll
            for (int mt = 0; mt < 4; ++mt)
                #pragma unroll
                for (int nt = 0; nt < 8; ++nt)
                    #pragma unroll
                    for (int q = 0; q < 4; ++q) acc[mt][nt][q] = 0.f;

            // ---- prefetch chunk 0
            {
                const int k0 = 0;
                const uint32_t so = sb;
                #pragma unroll
                for (int l = 0; l < 2; ++l) {
                    int q = tid + (l << 8);
                    int r = q >> 2, ch = q & 3;
                    uint32_t d = so + (uint32_t)(r*80 + ch*16);
                    size_t g = (size_t)(m0 + r) * 256 + k0 + ch*8;
                    cpasync16(d, Yh + g);
                    cpasync16(d + AL_OFF, Yl + g);
                }
                #pragma unroll
                for (int l = 0; l < 4; ++l) {
                    int q = tid + (l << 8);
                    int n = q >> 2, ch = q & 3;
                    uint32_t d = so + B_OFF + (uint32_t)(n*80 + ch*16);
                    size_t g = (size_t)n * 256 + k0 + ch*8;
                    cpasync16(d, curh + g);
                    cpasync16(d + 20480u, curl + g);
                }
                cp_commit();
            }

            #pragma unroll 1
            for (int kc = 0; kc < 8; ++kc) {
                if (kc < 7) {       // prefetch next chunk into other stage
                    const int k0 = (kc + 1) << 5;
                    const uint32_t so = sb + ((kc + 1) & 1) * STAGE;
                    #pragma unroll
                    for (int l = 0; l < 2; ++l) {
                        int q = tid + (l << 8);
                        int r = q >> 2, ch = q & 3;
                        uint32_t d = so + (uint32_t)(r*80 + ch*16);
                        size_t g = (size_t)(m0 + r) * 256 + k0 + ch*8;
                        cpasync16(d, Yh + g);
                        cpasync16(d + AL_OFF, Yl + g);
                    }
                    #pragma unroll
                    for (int l = 0; l < 4; ++l) {
                        int q = tid + (l << 8);
                        int n = q >> 2, ch = q & 3;
                        uint32_t d = so + B_OFF + (uint32_t)(n*80 + ch*16);
                        size_t g = (size_t)n * 256 + k0 + ch*8;
                        cpasync16(d, curh + g);
                        cpasync16(d + 20480u, curl + g);
                    }
                    cp_commit();
                    cp_wait<1>();
                } else {
                    cp_wait<0>();
                }
                __syncthreads();

                const uint32_t stg = (uint32_t)(kc & 1) * STAGE;
                #pragma unroll
                for (int ks = 0; ks < 2; ++ks) {       // two k16 steps
                    const uint32_t kb = (uint32_t)(ks << 5);   // 0 / 32 bytes
                    uint32_t ah[4][4], al[4][4];
                    #pragma unroll
                    for (int mt = 0; mt < 4; ++mt) {
                        uint32_t a = aA0 + stg + (uint32_t)(mt * 1280) + kb;
                        ldsm4(ah[mt][0], ah[mt][1], ah[mt][2], ah[mt][3], a);
                        ldsm4(al[mt][0], al[mt][1], al[mt][2], al[mt][3], a + AL_OFF);
                    }
                    #pragma unroll
                    for (int np = 0; np < 4; ++np) {
                        uint32_t a = aB0 + stg + (uint32_t)(np * 1280) + kb;
                        uint32_t bh0, bh1, bh2, bh3, bl0, bl1, bl2, bl3;
                        ldsm4(bh0, bh1, bh2, bh3, a);
                        ldsm4(bl0, bl1, bl2, bl3, a + 20480u);
                        #pragma unroll
                        for (int mt = 0; mt < 4; ++mt) {
                            mma16816(acc[mt][2*np+0], ah[mt], bh0, bh2);
                            mma16816(acc[mt][2*np+1], ah[mt], bh1, bh3);
                            mma16816(acc[mt][2*np+0], ah[mt], bl0, bl2);
                            mma16816(acc[mt][2*np+1], ah[mt], bl1, bl3);
                            mma16816(acc[mt][2*np+0], al[mt], bh0, bh2);
                            mma16816(acc[mt][2*np+1], al[mt], bh1, bh3);
                        }
                    }
                }
                __syncthreads();
            }

            // ---- epilogue: tn = 2*acc - Tprev ; F += ck*tn ; re-split tn ----
            #pragma unroll
            for (int mt = 0; mt < 4; ++mt) {
                #pragma unroll
                for (int nt = 0; nt < 8; ++nt) {
                    int r0 = m0 + wm0 + mt*16 + (lane >> 2);
                    int jj = wn0 + nt*8 + (lane & 3)*2;
                    #pragma unroll
                    for (int hrow = 0; hrow < 2; ++hrow) {
                        int r = r0 + hrow*8;
                        float d0 = acc[mt][nt][hrow*2 + 0];
                        float d1 = acc[mt][nt][hrow*2 + 1];
                        size_t idx = (size_t)r * 256 + jj;
                        uint32_t hb = *(const uint32_t*)(dsth + idx);
                        uint32_t lb = *(const uint32_t*)(dstl + idx);
                        float tp0 = __bfloat162float(__ushort_as_bfloat16((unsigned short)(hb & 0xffff)))
                                  + __bfloat162float(__ushort_as_bfloat16((unsigned short)(lb & 0xffff)));
                        float tp1 = __bfloat162float(__ushort_as_bfloat16((unsigned short)(hb >> 16)))
                                  + __bfloat162float(__ushort_as_bfloat16((unsigned short)(lb >> 16)));
                        float tn0 = 2.f*d0 - tp0;
                        float tn1 = 2.f*d1 - tp1;
                        float2 f = *(float2*)(Fm + idx);
                        f.x += ck*tn0;  f.y += ck*tn1;
                        *(float2*)(Fm + idx) = f;
                        __nv_bfloat16 h0 = __float2bfloat16(tn0);
                        __nv_bfloat16 e0 = __float2bfloat16(tn0 - __bfloat162float(h0));
                        __nv_bfloat16 h1 = __float2bfloat16(tn1);
                        __nv_bfloat16 e1 = __float2bfloat16(tn1 - __bfloat162float(h1));
                        *(uint32_t*)(dsth + idx) =
                            (uint32_t)__bfloat16_as_ushort(h0) | ((uint32_t)__bfloat16_as_ushort(h1) << 16);
                        *(uint32_t*)(dstl + idx) =
                            (uint32_t)__bfloat16_as_ushort(e0) | ((uint32_t)__bfloat16_as_ushort(e1) << 16);
                    }
                }
            }
            __syncthreads();
        }
    }
}

// ---------------- tails ------------------------------------------------------
__global__ void center_kernel() {
    int t = blockIdx.x * blockDim.x + threadIdx.x;
    float4 s = make_float4(0.f, 0.f, 0.f, 0.f);
    for (int b = 0; b < BATCH; ++b) {
        float4 v = ((const float4*)(g_F + (size_t)b*MATSZ))[t];
        s.x += v.x; s.y += v.y; s.z += v.z; s.w += v.w;
    }
    const float inv = 1.f / BATCH;
    s.x *= inv; s.y *= inv; s.z *= inv; s.w *= inv;
    ((float4*)g_center)[t] = s;
}

__global__ void out_kernel(float* __restrict__ out) {
    int c = blockIdx.x, b = blockIdx.y;
    const float4* F4 = (const float4*)(g_F  + (size_t)b*MATSZ);
    const float4* W4 = (const float4*)(g_Ws + (size_t)c*MATSZ);
    float acc = 0.f;
    for (int t = threadIdx.x; t < MATSZ/4; t += 256) {
        float4 f = F4[t], w = W4[t];
        acc += f.x*w.x + f.y*w.y + f.z*w.z + f.w*w.w;
    }
    __shared__ float red[8];
    #pragma unroll
    for (int o = 16; o; o >>= 1) acc += __shfl_down_sync(0xffffffffu, acc, o);
    if ((threadIdx.x & 31) == 0) red[threadIdx.x >> 5] = acc;
    __syncthreads();
    if (threadIdx.x < 8) {
        float v = red[threadIdx.x];
        #pragma unroll
        for (int o = 4; o; o >>= 1) v += __shfl_down_sync(0xffu, v, o);
        if (threadIdx.x == 0) out[b*CC + c] = v;
    }
}

__global__ void p_kernel() {
    int c  = blockIdx.y;
    int r0 = blockIdx.x * 32;
    __shared__ float Wb[32][256];
    for (int l = 0; l < 32; ++l)
        Wb[l][threadIdx.x] = g_Ws[(size_t)c*MATSZ + (size_t)(r0+l)*256 + threadIdx.x];
    __syncthreads();
    int j = threadIdx.x;
    float acc[32];
    #pragma unroll
    for (int ii = 0; ii < 32; ++ii) acc[ii] = 0.f;
    for (int k = 0; k < 256; ++k) {
        float bv = g_center[k*256 + j];
        #pragma unroll
        for (int ii = 0; ii < 32; ++ii) acc[ii] += Wb[ii][k] * bv;
    }
    for (int ii = 0; ii < 32; ++ii)
        g_P[(size_t)c*MATSZ + (size_t)(r0+ii)*256 + j] = acc[ii];
}

__global__ void g_kernel() {
    int c = blockIdx.x;
    const float* P = g_P + (size_t)c*MATSZ;
    float acc = 0.f;
    for (int idx = threadIdx.x; idx < MATSZ; idx += 256) {
        int i = idx >> 8, j = idx & 255;
        acc += P[idx] * P[j*256 + i];
    }
    __shared__ float red[8];
    #pragma unroll
    for (int o = 16; o; o >>= 1) acc += __shfl_down_sync(0xffffffffu, acc, o);
    if ((threadIdx.x & 31) == 0) red[threadIdx.x >> 5] = acc;
    __syncthreads();
    if (threadIdx.x < 8) {
        float v = red[threadIdx.x];
        #pragma unroll
        for (int o = 4; o; o >>= 1) v += __shfl_down_sync(0xffu, v, o);
        if (threadIdx.x == 0) atomicAdd(&g_acc, v);
    }
}

__global__ void fin_kernel(float* __restrict__ out, int out_size) {
    out[out_size - 1] = g_acc * (1.f / CC);
}

// ---------------- host -------------------------------------------------------
extern "C" void kernel_launch(void* const* d_in, const int* in_sizes, int n_in,
                              void* d_out, int out_size) {
    const float* X = (const float*)d_in[0];
    const float* W = (const float*)d_in[1];
    float* out = (float*)d_out;

    const double a = 0.9, bb = 6.0;
    double coef[DEG+1];
    {
        const int N = 128;
        for (int k = 0; k <= DEG; ++k) {
            double s = 0.0;
            for (int j = 0; j < N; ++j) {
                double th  = M_PI * (j + 0.5) / N;
                double lam = 0.5*(bb+a) + 0.5*(bb-a)*cos(th);
                s += log(lam) * cos(k*th);
            }
            coef[k] = 2.0 / N * s;
        }
        coef[0] *= 0.5;
    }
    const float sc = (float)( 2.0/(bb-a));
    const float of = (float)(-(bb+a)/(bb-a));
    ChebArgs ca;
    for (int k = 0; k < NSTEPS; ++k) ca.c[k] = (float)coef[k+2];

    const int smem_bytes = 2 * STAGE;     // 122880
    cudaFuncSetAttribute(cheb_mma, cudaFuncAttributeMaxDynamicSharedMemorySize,
                         smem_bytes);

    prep_mats<<<(BATCH*MATSZ/4)/256, 256>>>(X, (float)coef[0], (float)coef[1], sc, of);
    prep_W<<<(CC*MATSZ)/256, 256>>>(W);
    cheb_mma<<<BATCH, 256, smem_bytes>>>(ca);
    center_kernel<<<(MATSZ/4)/256, 256>>>();
    out_kernel<<<dim3(CC, BATCH), 256>>>(out);
    p_kernel<<<dim3(8, CC), 256>>>();
    g_kernel<<<CC, 256>>>();
    fin_kernel<<<1, 1>>>(out, out_size);
}

// round 6
// speedup vs baseline: 2.2236x; 1.4638x over previous
#include <cuda_runtime.h>
#include <cuda_bf16.h>
#include <math.h>
#include <stdint.h>

#ifndef M_PI
#define M_PI 3.14159265358979323846
#endif

#define BATCH 128
#define HH    256
#define CC    10
#define MATSZ (HH*HH)
#define DEG   16
#define NSTEPS (DEG-1)            /* 15 recurrence steps: T2..T16 */

#define AL_OFF 10240u             /* 128*80 */
#define B_OFF  20480u
#define STAGE  61440u             /* A hi/lo 20480 + B hi/lo 40960 */
#define NSTAGE 3

// ---------------- scratch ----------------------------------------------------
__device__ __align__(16) __nv_bfloat16 g_Yh[BATCH*MATSZ];
__device__ __align__(16) __nv_bfloat16 g_Yl[BATCH*MATSZ];
__device__ __align__(16) __nv_bfloat16 g_S0h[BATCH*MATSZ];
__device__ __align__(16) __nv_bfloat16 g_S0l[BATCH*MATSZ];
__device__ __align__(16) __nv_bfloat16 g_S1h[BATCH*MATSZ];
__device__ __align__(16) __nv_bfloat16 g_S1l[BATCH*MATSZ];
__device__ float g_F [BATCH*MATSZ];
__device__ float g_Ws[CC*MATSZ];
__device__ float g_center[MATSZ];
__device__ float g_P [CC*MATSZ];
__device__ float g_acc;

struct ChebArgs { float c[NSTEPS]; };

// ---------------- PTX helpers ------------------------------------------------
__device__ __forceinline__ uint32_t smem_u32(const void* p) {
    uint32_t a;
    asm("{ .reg .u64 t; cvta.to.shared.u64 t, %1; cvt.u32.u64 %0, t; }"
        : "=r"(a) : "l"(p));
    return a;
}
__device__ __forceinline__ void cpasync16(uint32_t dst, const void* src) {
    asm volatile("cp.async.cg.shared.global [%0], [%1], 16;"
                 :: "r"(dst), "l"(src) : "memory");
}
__device__ __forceinline__ void cp_commit() {
    asm volatile("cp.async.commit_group;" ::: "memory");
}
template<int N> __device__ __forceinline__ void cp_wait() {
    asm volatile("cp.async.wait_group %0;" :: "n"(N) : "memory");
}
__device__ __forceinline__ void ldsm4(uint32_t& r0, uint32_t& r1,
                                      uint32_t& r2, uint32_t& r3, uint32_t a) {
    asm volatile("ldmatrix.sync.aligned.m8n8.x4.shared.b16 {%0,%1,%2,%3}, [%4];"
                 : "=r"(r0), "=r"(r1), "=r"(r2), "=r"(r3) : "r"(a));
}
__device__ __forceinline__ void mma16816(float* c, const uint32_t* a,
                                         uint32_t b0, uint32_t b1) {
    asm volatile(
        "mma.sync.aligned.m16n8k16.row.col.f32.bf16.bf16.f32 "
        "{%0,%1,%2,%3}, {%4,%5,%6,%7}, {%8,%9}, {%0,%1,%2,%3};"
        : "+f"(c[0]), "+f"(c[1]), "+f"(c[2]), "+f"(c[3])
        : "r"(a[0]), "r"(a[1]), "r"(a[2]), "r"(a[3]), "r"(b0), "r"(b1));
}

// ---------------- prep: Y = s*X + o*I ; split bf16 hi/lo; init slots, F -----
__global__ void prep_mats(const float* __restrict__ X,
                          float c0, float c1, float s, float o) {
    unsigned gid = blockIdx.x * blockDim.x + threadIdx.x;
    float4 x = ((const float4*)X)[gid];
    unsigned within = gid & (MATSZ/4 - 1);
    int i  = (int)(within >> 6);
    int j0 = (int)(within & 63) << 2;

    float id[4], y[4];
    id[0] = (i == j0+0) ? 1.f : 0.f;  id[1] = (i == j0+1) ? 1.f : 0.f;
    id[2] = (i == j0+2) ? 1.f : 0.f;  id[3] = (i == j0+3) ? 1.f : 0.f;
    y[0] = s*x.x + o*id[0];  y[1] = s*x.y + o*id[1];
    y[2] = s*x.z + o*id[2];  y[3] = s*x.w + o*id[3];

    float4 fv;
    fv.x = c0*id[0] + c1*y[0];  fv.y = c0*id[1] + c1*y[1];
    fv.z = c0*id[2] + c1*y[2];  fv.w = c0*id[3] + c1*y[3];
    ((float4*)g_F)[gid] = fv;

    unsigned hh[4], ll[4];
    #pragma unroll
    for (int q = 0; q < 4; ++q) {
        __nv_bfloat16 h = __float2bfloat16(y[q]);
        float hf = __bfloat162float(h);
        __nv_bfloat16 l = __float2bfloat16(y[q] - hf);
        hh[q] = __bfloat16_as_ushort(h);
        ll[q] = __bfloat16_as_ushort(l);
    }
    uint2 ph = make_uint2(hh[0] | (hh[1]<<16), hh[2] | (hh[3]<<16));
    uint2 pl = make_uint2(ll[0] | (ll[1]<<16), ll[2] | (ll[3]<<16));
    ((uint2*)g_Yh)[gid]  = ph;  ((uint2*)g_Yl)[gid]  = pl;
    ((uint2*)g_S1h)[gid] = ph;  ((uint2*)g_S1l)[gid] = pl;

    const unsigned one = 0x3F80u;
    uint2 pi = make_uint2(((i==j0+0)?one:0u) | (((i==j0+1)?one:0u)<<16),
                          ((i==j0+2)?one:0u) | (((i==j0+3)?one:0u)<<16));
    ((uint2*)g_S0h)[gid] = pi;
    ((uint2*)g_S0l)[gid] = make_uint2(0u, 0u);
    if (gid == 0) g_acc = 0.f;
}

__global__ void prep_W(const float* __restrict__ W) {
    int gid = blockIdx.x * blockDim.x + threadIdx.x;
    int c   = gid >> 16;
    int rem = gid & 65535;
    int i   = rem >> 8, j = rem & 255;
    g_Ws[gid] = 0.5f * (W[gid] + W[(c<<16) + (j<<8) + i]);
}

// ---------------- HMMA Chebyshev recurrence (512 thr, 3-stage pipeline) -----
__global__ void __launch_bounds__(512, 1) cheb_mma(ChebArgs args) {
    extern __shared__ char dsm[];
    const uint32_t sb = smem_u32(dsm);

    const int b    = blockIdx.x;
    const int tid  = threadIdx.x;
    const int wid  = tid >> 5;
    const int lane = tid & 31;
    const int wm0  = (wid >> 2) << 5;      // 0,32,64,96 within 128-row half
    const int wn0  = (wid & 3)  << 6;      // 0,64,128,192
    const int laneA  = lane & 15;
    const int laneHi = (lane >> 4) << 4;   // 0 or 16 bytes

    const size_t moff = (size_t)b * MATSZ;
    const __nv_bfloat16* Yh = g_Yh + moff;
    const __nv_bfloat16* Yl = g_Yl + moff;
    float* Fm = g_F + moff;

    const uint32_t aA0 = sb + (uint32_t)((wm0 + laneA) * 80) + (uint32_t)laneHi;
    const uint32_t aB0 = sb + B_OFF + (uint32_t)((wn0 + laneA) * 80) + (uint32_t)laneHi;

    // per-thread load coordinates
    const int lr = tid >> 2;               // 0..127 (A row)
    const int lc = (tid & 3) << 4;         // 0,16,32,48 byte chunk in 64B row

    #pragma unroll 1
    for (int step = 0; step < NSTEPS; ++step) {
        const float ck = args.c[step];
        const __nv_bfloat16 *curh, *curl;
        __nv_bfloat16 *dsth, *dstl;
        if ((step & 1) == 0) { curh = g_S1h+moff; curl = g_S1l+moff;
                               dsth = g_S0h+moff; dstl = g_S0l+moff; }
        else                 { curh = g_S0h+moff; curl = g_S0l+moff;
                               dsth = g_S1h+moff; dstl = g_S1l+moff; }

        #pragma unroll 1
        for (int half = 0; half < 2; ++half) {
            const int m0 = half << 7;

            float acc[2][8][4];
            #pragma unroll
            for (int mt = 0; mt < 2; ++mt)
                #pragma unroll
                for (int nt = 0; nt < 8; ++nt)
                    #pragma unroll
                    for (int q = 0; q < 4; ++q) acc[mt][nt][q] = 0.f;

            // ---- prologue: prefetch chunks 0 and 1
            #pragma unroll
            for (int pc = 0; pc < 2; ++pc) {
                const int k0 = pc << 5;
                const uint32_t so = sb + (uint32_t)pc * STAGE;
                {
                    uint32_t d = so + (uint32_t)(lr*80) + (uint32_t)lc;
                    size_t g = ((size_t)(m0 + lr) * 256 + k0) * 2 + lc;
                    cpasync16(d,          (const char*)Yh + g);
                    cpasync16(d + AL_OFF, (const char*)Yl + g);
                }
                #pragma unroll
                for (int l = 0; l < 2; ++l) {
                    int q = tid + (l << 9);
                    int n = q >> 2, ch = (q & 3) << 4;
                    uint32_t d = so + B_OFF + (uint32_t)(n*80 + ch);
                    size_t g = ((size_t)n * 256 + k0) * 2 + ch;
                    cpasync16(d,          (const char*)curh + g);
                    cpasync16(d + 20480u, (const char*)curl + g);
                }
                cp_commit();
            }

            #pragma unroll 1
            for (int kc = 0; kc < 8; ++kc) {
                if (kc < 6) {          // prefetch chunk kc+2
                    const int k0 = (kc + 2) << 5;
                    const uint32_t so = sb + (uint32_t)((kc + 2) % NSTAGE) * STAGE;
                    {
                        uint32_t d = so + (uint32_t)(lr*80) + (uint32_t)lc;
                        size_t g = ((size_t)(m0 + lr) * 256 + k0) * 2 + lc;
                        cpasync16(d,          (const char*)Yh + g);
                        cpasync16(d + AL_OFF, (const char*)Yl + g);
                    }
                    #pragma unroll
                    for (int l = 0; l < 2; ++l) {
                        int q = tid + (l << 9);
                        int n = q >> 2, ch = (q & 3) << 4;
                        uint32_t d = so + B_OFF + (uint32_t)(n*80 + ch);
                        size_t g = ((size_t)n * 256 + k0) * 2 + ch;
                        cpasync16(d,          (const char*)curh + g);
                        cpasync16(d + 20480u, (const char*)curl + g);
                    }
                    cp_commit();
                    cp_wait<2>();
                } else if (kc == 6) {
                    cp_wait<1>();
                } else {
                    cp_wait<0>();
                }
                __syncthreads();

                const uint32_t stg = (uint32_t)(kc % NSTAGE) * STAGE;
                #pragma unroll
                for (int ks = 0; ks < 2; ++ks) {
                    const uint32_t kb = (uint32_t)(ks << 5);
                    uint32_t ah[2][4], al[2][4];
                    #pragma unroll
                    for (int mt = 0; mt < 2; ++mt) {
                        uint32_t a = aA0 + stg + (uint32_t)(mt * 1280) + kb;
                        ldsm4(ah[mt][0], ah[mt][1], ah[mt][2], ah[mt][3], a);
                        ldsm4(al[mt][0], al[mt][1], al[mt][2], al[mt][3], a + AL_OFF);
                    }
                    #pragma unroll
                    for (int np = 0; np < 4; ++np) {
                        uint32_t a = aB0 + stg + (uint32_t)(np * 1280) + kb;
                        uint32_t bh0, bh1, bh2, bh3, bl0, bl1, bl2, bl3;
                        ldsm4(bh0, bh1, bh2, bh3, a);
                        ldsm4(bl0, bl1, bl2, bl3, a + 20480u);
                        #pragma unroll
                        for (int mt = 0; mt < 2; ++mt) {
                            mma16816(acc[mt][2*np+0], ah[mt], bh0, bh2);
                            mma16816(acc[mt][2*np+1], ah[mt], bh1, bh3);
                            mma16816(acc[mt][2*np+0], ah[mt], bl0, bl2);
                            mma16816(acc[mt][2*np+1], ah[mt], bl1, bl3);
                            mma16816(acc[mt][2*np+0], al[mt], bh0, bh2);
                            mma16816(acc[mt][2*np+1], al[mt], bh1, bh3);
                        }
                    }
                }
                __syncthreads();
            }

            // ---- epilogue: tn = 2*acc - Tprev ; F += ck*tn ; re-split tn ----
            #pragma unroll
            for (int mt = 0; mt < 2; ++mt) {
                #pragma unroll
                for (int nt = 0; nt < 8; ++nt) {
                    int r0 = m0 + wm0 + mt*16 + (lane >> 2);
                    int jj = wn0 + nt*8 + (lane & 3)*2;
                    #pragma unroll
                    for (int hrow = 0; hrow < 2; ++hrow) {
                        int r = r0 + hrow*8;
                        float d0 = acc[mt][nt][hrow*2 + 0];
                        float d1 = acc[mt][nt][hrow*2 + 1];
                        size_t idx = (size_t)r * 256 + jj;
                        uint32_t hb = *(const uint32_t*)(dsth + idx);
                        uint32_t lb = *(const uint32_t*)(dstl + idx);
                        float tp0 = __bfloat162float(__ushort_as_bfloat16((unsigned short)(hb & 0xffff)))
                                  + __bfloat162float(__ushort_as_bfloat16((unsigned short)(lb & 0xffff)));
                        float tp1 = __bfloat162float(__ushort_as_bfloat16((unsigned short)(hb >> 16)))
                                  + __bfloat162float(__ushort_as_bfloat16((unsigned short)(lb >> 16)));
                        float tn0 = 2.f*d0 - tp0;
                        float tn1 = 2.f*d1 - tp1;
                        float2 f = *(float2*)(Fm + idx);
                        f.x += ck*tn0;  f.y += ck*tn1;
                        *(float2*)(Fm + idx) = f;
                        __nv_bfloat16 h0 = __float2bfloat16(tn0);
                        __nv_bfloat16 e0 = __float2bfloat16(tn0 - __bfloat162float(h0));
                        __nv_bfloat16 h1 = __float2bfloat16(tn1);
                        __nv_bfloat16 e1 = __float2bfloat16(tn1 - __bfloat162float(h1));
                        *(uint32_t*)(dsth + idx) =
                            (uint32_t)__bfloat16_as_ushort(h0) | ((uint32_t)__bfloat16_as_ushort(h1) << 16);
                        *(uint32_t*)(dstl + idx) =
                            (uint32_t)__bfloat16_as_ushort(e0) | ((uint32_t)__bfloat16_as_ushort(e1) << 16);
                    }
                }
            }
            __syncthreads();
        }
    }
}

// ---------------- tails ------------------------------------------------------
__global__ void center_kernel() {
    int t = blockIdx.x * blockDim.x + threadIdx.x;
    float4 s0 = make_float4(0.f,0.f,0.f,0.f), s1 = s0, s2 = s0, s3 = s0;
    #pragma unroll 1
    for (int b = 0; b < BATCH; b += 4) {
        float4 v0 = ((const float4*)(g_F + (size_t)(b+0)*MATSZ))[t];
        float4 v1 = ((const float4*)(g_F + (size_t)(b+1)*MATSZ))[t];
        float4 v2 = ((const float4*)(g_F + (size_t)(b+2)*MATSZ))[t];
        float4 v3 = ((const float4*)(g_F + (size_t)(b+3)*MATSZ))[t];
        s0.x += v0.x; s0.y += v0.y; s0.z += v0.z; s0.w += v0.w;
        s1.x += v1.x; s1.y += v1.y; s1.z += v1.z; s1.w += v1.w;
        s2.x += v2.x; s2.y += v2.y; s2.z += v2.z; s2.w += v2.w;
        s3.x += v3.x; s3.y += v3.y; s3.z += v3.z; s3.w += v3.w;
    }
    const float inv = 1.f / BATCH;
    float4 s;
    s.x = (s0.x+s1.x+s2.x+s3.x)*inv;  s.y = (s0.y+s1.y+s2.y+s3.y)*inv;
    s.z = (s0.z+s1.z+s2.z+s3.z)*inv;  s.w = (s0.w+s1.w+s2.w+s3.w)*inv;
    ((float4*)g_center)[t] = s;
}

// one block per b; F read once, Ws (2.5MB) L2-resident
__global__ void out_kernel(float* __restrict__ out) {
    int b = blockIdx.x;
    const float4* F4 = (const float4*)(g_F + (size_t)b*MATSZ);
    float acc[CC];
    #pragma unroll
    for (int c = 0; c < CC; ++c) acc[c] = 0.f;
    for (int t = threadIdx.x; t < MATSZ/4; t += 256) {
        float4 f = F4[t];
        #pragma unroll
        for (int c = 0; c < CC; ++c) {
            float4 w = ((const float4*)(g_Ws + (size_t)c*MATSZ))[t];
            acc[c] += f.x*w.x + f.y*w.y + f.z*w.z + f.w*w.w;
        }
    }
    __shared__ float red[8][CC];
    #pragma unroll
    for (int c = 0; c < CC; ++c) {
        float v = acc[c];
        #pragma unroll
        for (int o = 16; o; o >>= 1) v += __shfl_down_sync(0xffffffffu, v, o);
        if ((threadIdx.x & 31) == 0) red[threadIdx.x >> 5][c] = v;
    }
    __syncthreads();
    if (threadIdx.x < CC) {
        float v = 0.f;
        #pragma unroll
        for (int w = 0; w < 8; ++w) v += red[w][threadIdx.x];
        out[b*CC + threadIdx.x] = v;
    }
}

__global__ void p_kernel() {
    int c  = blockIdx.y;
    int r0 = blockIdx.x * 32;
    __shared__ float Wb[32][256];
    for (int l = 0; l < 32; ++l)
        Wb[l][threadIdx.x] = g_Ws[(size_t)c*MATSZ + (size_t)(r0+l)*256 + threadIdx.x];
    __syncthreads();
    int j = threadIdx.x;
    float acc[32];
    #pragma unroll
    for (int ii = 0; ii < 32; ++ii) acc[ii] = 0.f;
    for (int k = 0; k < 256; ++k) {
        float bv = g_center[k*256 + j];
        #pragma unroll
        for (int ii = 0; ii < 32; ++ii) acc[ii] += Wb[ii][k] * bv;
    }
    for (int ii = 0; ii < 32; ++ii)
        g_P[(size_t)c*MATSZ + (size_t)(r0+ii)*256 + j] = acc[ii];
}

__global__ void g_kernel() {
    int c = blockIdx.x;
    const float* P = g_P + (size_t)c*MATSZ;
    float acc = 0.f;
    for (int idx = threadIdx.x; idx < MATSZ; idx += 256) {
        int i = idx >> 8, j = idx & 255;
        acc += P[idx] * P[j*256 + i];
    }
    __shared__ float red[8];
    #pragma unroll
    for (int o = 16; o; o >>= 1) acc += __shfl_down_sync(0xffffffffu, acc, o);
    if ((threadIdx.x & 31) == 0) red[threadIdx.x >> 5] = acc;
    __syncthreads();
    if (threadIdx.x < 8) {
        float v = red[threadIdx.x];
        #pragma unroll
        for (int o = 4; o; o >>= 1) v += __shfl_down_sync(0xffu, v, o);
        if (threadIdx.x == 0) atomicAdd(&g_acc, v);
    }
}

__global__ void fin_kernel(float* __restrict__ out, int out_size) {
    out[out_size - 1] = g_acc * (1.f / CC);
}

// ---------------- host -------------------------------------------------------
extern "C" void kernel_launch(void* const* d_in, const int* in_sizes, int n_in,
                              void* d_out, int out_size) {
    const float* X = (const float*)d_in[0];
    const float* W = (const float*)d_in[1];
    float* out = (float*)d_out;

    // spectrum of X = A A^T/H + I is in [1, ~5.2]; interval with margin:
    const double a = 0.98, bb = 5.4;
    double coef[DEG+1];
    {
        const int N = 128;
        for (int k = 0; k <= DEG; ++k) {
            double s = 0.0;
            for (int j = 0; j < N; ++j) {
                double th  = M_PI * (j + 0.5) / N;
                double lam = 0.5*(bb+a) + 0.5*(bb-a)*cos(th);
                s += log(lam) * cos(k*th);
            }
            coef[k] = 2.0 / N * s;
        }
        coef[0] *= 0.5;
    }
    const float sc = (float)( 2.0/(bb-a));
    const float of = (float)(-(bb+a)/(bb-a));
    ChebArgs ca;
    for (int k = 0; k < NSTEPS; ++k) ca.c[k] = (float)coef[k+2];

    const int smem_bytes = NSTAGE * STAGE;    // 184320
    cudaFuncSetAttribute(cheb_mma, cudaFuncAttributeMaxDynamicSharedMemorySize,
                         smem_bytes);

    prep_mats<<<(BATCH*MATSZ/4)/256, 256>>>(X, (float)coef[0], (float)coef[1], sc, of);
    prep_W<<<(CC*MATSZ)/256, 256>>>(W);
    cheb_mma<<<BATCH, 512, smem_bytes>>>(ca);
    center_kernel<<<(MATSZ/4)/256, 256>>>();
    out_kernel<<<BATCH, 256>>>(out);
    p_kernel<<<dim3(8, CC), 256>>>();
    g_kernel<<<CC, 256>>>();
    fin_kernel<<<1, 1>>>(out, out_size);
}

// round 8
// speedup vs baseline: 3.2877x; 1.4786x over previous
#include <cuda_runtime.h>
#include <cuda_bf16.h>
#include <math.h>
#include <stdint.h>

#ifndef M_PI
#define M_PI 3.14159265358979323846
#endif

#define BATCH 128
#define HH    256
#define CC    10
#define MATSZ (HH*HH)
#define DEG   16
#define NSTEPS (DEG-1)            /* 15 steps: T2..T16 */

// ---- smem layout (bytes). Row pads chosen for conflict-free ldmatrix. ----
#define YROW    528               /* 256 k-elems * 2B + 16B pad  */
#define STGROW  48                /* 16 k-elems * 2B + 16B pad   */
#define YH_OFF  0
#define B_HI    135168            /* 256*528                      */
#define B_LO    (B_HI + 64*528)   /* +33792                       */
#define STG_OFF (B_HI + 2*64*528) /* 202752                       */
#define STG_SZ  (256*STGROW)      /* 12288                        */
#define SMEM_TOTAL (STG_OFF + 2*STG_SZ)   /* 227328 */

// ---------------- scratch ----------------------------------------------------
__device__ __align__(16) __nv_bfloat16 g_Yh[BATCH*MATSZ];
__device__ __align__(16) __nv_bfloat16 g_Yl[BATCH*MATSZ];
__device__ float g_F [BATCH*MATSZ];
__device__ float g_Ws[CC*MATSZ];
__device__ float g_center[MATSZ];
__device__ float g_P [CC*MATSZ];
__device__ float g_acc;

struct ChebArgs { float c0, c1; float c[NSTEPS]; };

// ---------------- PTX helpers ------------------------------------------------
__device__ __forceinline__ uint32_t smem_u32(const void* p) {
    uint32_t a;
    asm("{ .reg .u64 t; cvta.to.shared.u64 t, %1; cvt.u32.u64 %0, t; }"
        : "=r"(a) : "l"(p));
    return a;
}
__device__ __forceinline__ void cpasync16(uint32_t dst, const void* src) {
    asm volatile("cp.async.cg.shared.global [%0], [%1], 16;"
                 :: "r"(dst), "l"(src) : "memory");
}
__device__ __forceinline__ void cp_commit() {
    asm volatile("cp.async.commit_group;" ::: "memory");
}
template<int N> __device__ __forceinline__ void cp_wait() {
    asm volatile("cp.async.wait_group %0;" :: "n"(N) : "memory");
}
__device__ __forceinline__ void ldsm4(uint32_t& r0, uint32_t& r1,
                                      uint32_t& r2, uint32_t& r3, uint32_t a) {
    asm volatile("ldmatrix.sync.aligned.m8n8.x4.shared.b16 {%0,%1,%2,%3}, [%4];"
                 : "=r"(r0), "=r"(r1), "=r"(r2), "=r"(r3) : "r"(a));
}
__device__ __forceinline__ void mma16816(float* c, const uint32_t* a,
                                         uint32_t b0, uint32_t b1) {
    asm volatile(
        "mma.sync.aligned.m16n8k16.row.col.f32.bf16.bf16.f32 "
        "{%0,%1,%2,%3}, {%4,%5,%6,%7}, {%8,%9}, {%0,%1,%2,%3};"
        : "+f"(c[0]), "+f"(c[1]), "+f"(c[2]), "+f"(c[3])
        : "r"(a[0]), "r"(a[1]), "r"(a[2]), "r"(a[3]), "r"(b0), "r"(b1));
}

// ---------------- prep: Y = s*X + o*I, split bf16 hi/lo ---------------------
__global__ void prep_mats(const float* __restrict__ X, float s, float o) {
    unsigned gid = blockIdx.x * blockDim.x + threadIdx.x;
    float4 x = ((const float4*)X)[gid];
    unsigned within = gid & (MATSZ/4 - 1);
    int i  = (int)(within >> 6);
    int j0 = (int)(within & 63) << 2;

    float y[4];
    y[0] = s*x.x + ((i==j0+0)?o:0.f);  y[1] = s*x.y + ((i==j0+1)?o:0.f);
    y[2] = s*x.z + ((i==j0+2)?o:0.f);  y[3] = s*x.w + ((i==j0+3)?o:0.f);

    unsigned hh[4], ll[4];
    #pragma unroll
    for (int q = 0; q < 4; ++q) {
        __nv_bfloat16 h = __float2bfloat16(y[q]);
        __nv_bfloat16 l = __float2bfloat16(y[q] - __bfloat162float(h));
        hh[q] = __bfloat16_as_ushort(h);
        ll[q] = __bfloat16_as_ushort(l);
    }
    ((uint2*)g_Yh)[gid] = make_uint2(hh[0] | (hh[1]<<16), hh[2] | (hh[3]<<16));
    ((uint2*)g_Yl)[gid] = make_uint2(ll[0] | (ll[1]<<16), ll[2] | (ll[3]<<16));
    if (gid == 0) g_acc = 0.f;
}

__global__ void prep_W(const float* __restrict__ W) {
    int gid = blockIdx.x * blockDim.x + threadIdx.x;
    int c   = gid >> 16;
    int rem = gid & 65535;
    int i   = rem >> 8, j = rem & 255;
    g_Ws[gid] = 0.5f * (W[gid] + W[(c<<16) + (j<<8) + i]);
}

// ---------------- Chebyshev recurrence, column-slice resident ----------------
// CTA = (slice, b): computes T[:, slice*64 .. +64) for all steps.
// Yhi resident smem; Ylo streamed (L2-hot); T slice lives in B smem;
// Tprev and F live in registers across all steps.
// Recurrence state: B smem holds T_k (hi/lo), tp regs hold T_{k-1}.
// Epilogue: tn = 2*acc - tp; F += ck*tn; tp = (old B value = T_k); B = split(tn).
__global__ void __launch_bounds__(256, 1) cheb_mma(ChebArgs args) {
    extern __shared__ char dsm[];
    const uint32_t sb = smem_u32(dsm);

    const int slice = blockIdx.x;          // 0..3
    const int b     = blockIdx.y;          // 0..127
    const int tid   = threadIdx.x;
    const int w     = tid >> 5;            // 8 warps: warp rows [w*32, w*32+32)
    const int lane  = tid & 31;
    const int laneA = lane & 15;
    const int laneHi = (lane >> 4) << 4;
    const int n0g   = slice << 6;

    const size_t moff = (size_t)b * MATSZ;
    const char* Yh = (const char*)(g_Yh + moff);
    const char* Yl = (const char*)(g_Yl + moff);

    // ---- init: Yhi resident (256 rows x 512B) + B init (T1 = Y[:, slice]) --
    #pragma unroll
    for (int i = 0; i < 32; ++i) {
        int op = tid + (i << 8);           // 0..8191
        int r = op >> 5, ch = (op & 31) << 4;
        cpasync16(sb + YH_OFF + r*YROW + ch, Yh + r*512 + ch);
    }
    #pragma unroll
    for (int i = 0; i < 8; ++i) {
        int op = tid + (i << 8);           // 0..2047
        int n = op >> 5, ch = (op & 31) << 4;
        // B[n][k] = Y[k][n0g+n] = Y[n0g+n][k]  (Y exactly symmetric in fp32,
        // and the hi/lo split of a symmetric fp32 matrix is symmetric)
        cpasync16(sb + B_HI + n*YROW + ch, Yh + (size_t)(n0g + n)*512 + ch);
        cpasync16(sb + B_LO + n*YROW + ch, Yl + (size_t)(n0g + n)*512 + ch);
    }
    cp_commit();
    cp_wait<0>();
    __syncthreads();

    // ---- F, Tprev in registers (fragment layout) ----
    float F[2][8][4], tp[2][8][4];
    #pragma unroll
    for (int mt = 0; mt < 2; ++mt)
        #pragma unroll
        for (int nt = 0; nt < 8; ++nt)
            #pragma unroll
            for (int q = 0; q < 4; ++q) {
                int r  = w*32 + mt*16 + (lane >> 2) + ((q >> 1) << 3);
                int nl = nt*8 + ((lane & 3) << 1) + (q & 1);
                float yh = __bfloat162float(*(const __nv_bfloat16*)(dsm + B_HI + nl*YROW + r*2));
                float yl = __bfloat162float(*(const __nv_bfloat16*)(dsm + B_LO + nl*YROW + r*2));
                float idv = (r == n0g + nl) ? 1.f : 0.f;
                F [mt][nt][q] = args.c0*idv + args.c1*(yh + yl);
                tp[mt][nt][q] = idv;       // T0 = I
            }

    const uint32_t aAhi = sb + YH_OFF + (w*32 + laneA)*YROW + laneHi;
    const uint32_t aStg = (w*32 + laneA)*STGROW + laneHi;
    const uint32_t aB   = sb + B_HI + laneA*YROW + laneHi;

    #pragma unroll 1
    for (int step = 0; step < NSTEPS; ++step) {
        const float ck = args.c[step];
        float acc[2][8][4];
        #pragma unroll
        for (int mt = 0; mt < 2; ++mt)
            #pragma unroll
            for (int nt = 0; nt < 8; ++nt)
                #pragma unroll
                for (int q = 0; q < 4; ++q) acc[mt][nt][q] = 0.f;

        // prologue: stage Ylo chunk 0 (rows 0..255, 32B each)
        {
            uint32_t d = sb + STG_OFF + tid*STGROW;
            cpasync16(d,      Yl + tid*512);
            cpasync16(d + 16, Yl + tid*512 + 16);
            cp_commit();
        }

        #pragma unroll 1
        for (int kc = 0; kc < 16; ++kc) {
            if (kc < 15) {
                uint32_t d = sb + STG_OFF + ((kc + 1) & 1)*STG_SZ + tid*STGROW;
                const char* s = Yl + tid*512 + (kc + 1)*32;
                cpasync16(d,      s);
                cpasync16(d + 16, s + 16);
                cp_commit();
                cp_wait<1>();
            } else {
                cp_wait<0>();
            }
            __syncthreads();

            const uint32_t stg = sb + STG_OFF + (kc & 1)*STG_SZ;
            const uint32_t kb  = (uint32_t)(kc << 5);     // byte offset of k16

            uint32_t ah[2][4], al[2][4];
            #pragma unroll
            for (int mt = 0; mt < 2; ++mt) {
                ldsm4(ah[mt][0], ah[mt][1], ah[mt][2], ah[mt][3],
                      aAhi + (uint32_t)(mt*16*YROW) + kb);
                ldsm4(al[mt][0], al[mt][1], al[mt][2], al[mt][3],
                      stg + aStg + (uint32_t)(mt*16*STGROW));
            }
            #pragma unroll
            for (int np = 0; np < 4; ++np) {
                uint32_t a = aB + (uint32_t)(np*16*YROW) + kb;
                uint32_t bh0, bh1, bh2, bh3, bl0, bl1, bl2, bl3;
                ldsm4(bh0, bh1, bh2, bh3, a);
                ldsm4(bl0, bl1, bl2, bl3, a + (uint32_t)(64*YROW));
                #pragma unroll
                for (int mt = 0; mt < 2; ++mt) {
                    mma16816(acc[mt][2*np+0], ah[mt], bh0, bh2);
                    mma16816(acc[mt][2*np+1], ah[mt], bh1, bh3);
                    mma16816(acc[mt][2*np+0], ah[mt], bl0, bl2);
                    mma16816(acc[mt][2*np+1], ah[mt], bl1, bl3);
                    mma16816(acc[mt][2*np+0], al[mt], bh0, bh2);
                    mma16816(acc[mt][2*np+1], al[mt], bh1, bh3);
                }
            }
            __syncthreads();   // all reads done before staging reuse / B overwrite
        }

        // ---- epilogue: tn = 2*acc - tp ; F += ck*tn ;
        //      tp = T_k (old B value, read BEFORE overwrite) ; B = split(tn)
        #pragma unroll
        for (int mt = 0; mt < 2; ++mt)
            #pragma unroll
            for (int nt = 0; nt < 8; ++nt)
                #pragma unroll
                for (int q = 0; q < 4; ++q) {
                    int r  = w*32 + mt*16 + (lane >> 2) + ((q >> 1) << 3);
                    int nl = nt*8 + ((lane & 3) << 1) + (q & 1);
                    __nv_bfloat16* ph = (__nv_bfloat16*)(dsm + B_HI + nl*YROW + r*2);
                    __nv_bfloat16* pl = (__nv_bfloat16*)(dsm + B_LO + nl*YROW + r*2);
                    float told = __bfloat162float(*ph) + __bfloat162float(*pl);
                    float tn = 2.f*acc[mt][nt][q] - tp[mt][nt][q];
                    F [mt][nt][q] += ck * tn;
                    tp[mt][nt][q]  = told;          // T_{k-1} <- T_k
                    __nv_bfloat16 h = __float2bfloat16(tn);
                    __nv_bfloat16 l = __float2bfloat16(tn - __bfloat162float(h));
                    *ph = h;
                    *pl = l;
                }
        __syncthreads();       // B ready for next step
    }

    // ---- write F slice to gmem (once) ----
    float* Fm = g_F + moff;
    #pragma unroll
    for (int mt = 0; mt < 2; ++mt)
        #pragma unroll
        for (int nt = 0; nt < 8; ++nt)
            #pragma unroll
            for (int hrow = 0; hrow < 2; ++hrow) {
                int r  = w*32 + mt*16 + (lane >> 2) + hrow*8;
                int nl = nt*8 + ((lane & 3) << 1);
                *(float2*)(Fm + (size_t)r*256 + n0g + nl) =
                    make_float2(F[mt][nt][hrow*2], F[mt][nt][hrow*2+1]);
            }
}

// ---------------- tails ------------------------------------------------------
__global__ void center_kernel() {
    int t = blockIdx.x * blockDim.x + threadIdx.x;
    float4 s0 = make_float4(0.f,0.f,0.f,0.f), s1 = s0, s2 = s0, s3 = s0;
    #pragma unroll 1
    for (int b = 0; b < BATCH; b += 4) {
        float4 v0 = ((const float4*)(g_F + (size_t)(b+0)*MATSZ))[t];
        float4 v1 = ((const float4*)(g_F + (size_t)(b+1)*MATSZ))[t];
        float4 v2 = ((const float4*)(g_F + (size_t)(b+2)*MATSZ))[t];
        float4 v3 = ((const float4*)(g_F + (size_t)(b+3)*MATSZ))[t];
        s0.x += v0.x; s0.y += v0.y; s0.z += v0.z; s0.w += v0.w;
        s1.x += v1.x; s1.y += v1.y; s1.z += v1.z; s1.w += v1.w;
        s2.x += v2.x; s2.y += v2.y; s2.z += v2.z; s2.w += v2.w;
        s3.x += v3.x; s3.y += v3.y; s3.z += v3.z; s3.w += v3.w;
    }
    const float inv = 1.f / BATCH;
    float4 s;
    s.x = (s0.x+s1.x+s2.x+s3.x)*inv;  s.y = (s0.y+s1.y+s2.y+s3.y)*inv;
    s.z = (s0.z+s1.z+s2.z+s3.z)*inv;  s.w = (s0.w+s1.w+s2.w+s3.w)*inv;
    ((float4*)g_center)[t] = s;
}

__global__ void out_kernel(float* __restrict__ out) {
    int b = blockIdx.x;
    const float4* F4 = (const float4*)(g_F + (size_t)b*MATSZ);
    float acc[CC];
    #pragma unroll
    for (int c = 0; c < CC; ++c) acc[c] = 0.f;
    for (int t = threadIdx.x; t < MATSZ/4; t += 256) {
        float4 f = F4[t];
        #pragma unroll
        for (int c = 0; c < CC; ++c) {
            float4 w = ((const float4*)(g_Ws + (size_t)c*MATSZ))[t];
            acc[c] += f.x*w.x + f.y*w.y + f.z*w.z + f.w*w.w;
        }
    }
    __shared__ float red[8][CC];
    #pragma unroll
    for (int c = 0; c < CC; ++c) {
        float v = acc[c];
        #pragma unroll
        for (int o = 16; o; o >>= 1) v += __shfl_down_sync(0xffffffffu, v, o);
        if ((threadIdx.x & 31) == 0) red[threadIdx.x >> 5][c] = v;
    }
    __syncthreads();
    if (threadIdx.x < CC) {
        float v = 0.f;
        #pragma unroll
        for (int w = 0; w < 8; ++w) v += red[w][threadIdx.x];
        out[b*CC + threadIdx.x] = v;
    }
}

__global__ void p_kernel() {
    int c  = blockIdx.y;
    int r0 = blockIdx.x * 32;
    __shared__ float Wb[32][256];
    for (int l = 0; l < 32; ++l)
        Wb[l][threadIdx.x] = g_Ws[(size_t)c*MATSZ + (size_t)(r0+l)*256 + threadIdx.x];
    __syncthreads();
    int j = threadIdx.x;
    float acc[32];
    #pragma unroll
    for (int ii = 0; ii < 32; ++ii) acc[ii] = 0.f;
    for (int k = 0; k < 256; ++k) {
        float bv = g_center[k*256 + j];
        #pragma unroll
        for (int ii = 0; ii < 32; ++ii) acc[ii] += Wb[ii][k] * bv;
    }
    for (int ii = 0; ii < 32; ++ii)
        g_P[(size_t)c*MATSZ + (size_t)(r0+ii)*256 + j] = acc[ii];
}

__global__ void g_kernel() {
    int c = blockIdx.x;
    const float* P = g_P + (size_t)c*MATSZ;
    float acc = 0.f;
    for (int idx = threadIdx.x; idx < MATSZ; idx += 256) {
        int i = idx >> 8, j = idx & 255;
        acc += P[idx] * P[j*256 + i];
    }
    __shared__ float red[8];
    #pragma unroll
    for (int o = 16; o; o >>= 1) acc += __shfl_down_sync(0xffffffffu, acc, o);
    if ((threadIdx.x & 31) == 0) red[threadIdx.x >> 5] = acc;
    __syncthreads();
    if (threadIdx.x < 8) {
        float v = red[threadIdx.x];
        #pragma unroll
        for (int o = 4; o; o >>= 1) v += __shfl_down_sync(0xffu, v, o);
        if (threadIdx.x == 0) atomicAdd(&g_acc, v);
    }
}

__global__ void fin_kernel(float* __restrict__ out, int out_size) {
    out[out_size - 1] = g_acc * (1.f / CC);
}

// ---------------- host -------------------------------------------------------
extern "C" void kernel_launch(void* const* d_in, const int* in_sizes, int n_in,
                              void* d_out, int out_size) {
    const float* X = (const float*)d_in[0];
    const float* W = (const float*)d_in[1];
    float* out = (float*)d_out;

    const double a = 0.98, bb = 5.4;
    double coef[DEG+1];
    {
        const int N = 128;
        for (int k = 0; k <= DEG; ++k) {
            double s = 0.0;
            for (int j = 0; j < N; ++j) {
                double th  = M_PI * (j + 0.5) / N;
                double lam = 0.5*(bb+a) + 0.5*(bb-a)*cos(th);
                s += log(lam) * cos(k*th);
            }
            coef[k] = 2.0 / N * s;
        }
        coef[0] *= 0.5;
    }
    const float sc = (float)( 2.0/(bb-a));
    const float of = (float)(-(bb+a)/(bb-a));
    ChebArgs ca;
    ca.c0 = (float)coef[0];
    ca.c1 = (float)coef[1];
    for (int k = 0; k < NSTEPS; ++k) ca.c[k] = (float)coef[k+2];

    cudaFuncSetAttribute(cheb_mma, cudaFuncAttributeMaxDynamicSharedMemorySize,
                         SMEM_TOTAL);

    prep_mats<<<(BATCH*MATSZ/4)/256, 256>>>(X, sc, of);
    prep_W<<<(CC*MATSZ)/256, 256>>>(W);
    cheb_mma<<<dim3(4, BATCH), 256, SMEM_TOTAL>>>(ca);
    center_kernel<<<(MATSZ/4)/256, 256>>>();
    out_kernel<<<BATCH, 256>>>(out);
    p_kernel<<<dim3(8, CC), 256>>>();
    g_kernel<<<CC, 256>>>();
    fin_kernel<<<1, 1>>>(out, out_size);
}

// round 9
// speedup vs baseline: 5.4101x; 1.6456x over previous
#include <cuda_runtime.h>
#include <cuda_bf16.h>
#include <math.h>
#include <stdint.h>

#ifndef M_PI
#define M_PI 3.14159265358979323846
#endif

#define BATCH 128
#define HH    256
#define CC    10
#define MATSZ (HH*HH)
#define DEG   12
#define NSTEPS (DEG-1)            /* 11 steps: T2..T12 */

// ---- smem layout (bytes). 528-stride rows -> conflict-free ldmatrix. ----
#define YROW    528               /* 256 k-elems * 2B + 16B pad  */
#define YH_OFF  0
#define B_HI    135168            /* 256*528                      */
#define B_LO    (B_HI + 64*528)
#define SMEM_TOTAL (B_HI + 2*64*528)      /* 202752 */

// ---------------- scratch ----------------------------------------------------
__device__ __align__(16) __nv_bfloat16 g_Yh[BATCH*MATSZ];
__device__ __align__(16) __nv_bfloat16 g_Yl[BATCH*MATSZ];
__device__ float g_F [BATCH*MATSZ];
__device__ float g_Ws[CC*MATSZ];
__device__ float g_center[MATSZ];
__device__ float g_P [CC*MATSZ];
__device__ float g_acc;

struct ChebArgs { float c0, c1; float c[NSTEPS]; };

// ---------------- PTX helpers ------------------------------------------------
__device__ __forceinline__ uint32_t smem_u32(const void* p) {
    uint32_t a;
    asm("{ .reg .u64 t; cvta.to.shared.u64 t, %1; cvt.u32.u64 %0, t; }"
        : "=r"(a) : "l"(p));
    return a;
}
__device__ __forceinline__ void cpasync16(uint32_t dst, const void* src) {
    asm volatile("cp.async.cg.shared.global [%0], [%1], 16;"
                 :: "r"(dst), "l"(src) : "memory");
}
__device__ __forceinline__ void cp_commit() {
    asm volatile("cp.async.commit_group;" ::: "memory");
}
template<int N> __device__ __forceinline__ void cp_wait() {
    asm volatile("cp.async.wait_group %0;" :: "n"(N) : "memory");
}
__device__ __forceinline__ void ldsm4(uint32_t& r0, uint32_t& r1,
                                      uint32_t& r2, uint32_t& r3, uint32_t a) {
    asm volatile("ldmatrix.sync.aligned.m8n8.x4.shared.b16 {%0,%1,%2,%3}, [%4];"
                 : "=r"(r0), "=r"(r1), "=r"(r2), "=r"(r3) : "r"(a));
}
__device__ __forceinline__ void mma16816(float* c, const uint32_t* a,
                                         uint32_t b0, uint32_t b1) {
    asm volatile(
        "mma.sync.aligned.m16n8k16.row.col.f32.bf16.bf16.f32 "
        "{%0,%1,%2,%3}, {%4,%5,%6,%7}, {%8,%9}, {%0,%1,%2,%3};"
        : "+f"(c[0]), "+f"(c[1]), "+f"(c[2]), "+f"(c[3])
        : "r"(a[0]), "r"(a[1]), "r"(a[2]), "r"(a[3]), "r"(b0), "r"(b1));
}

// ---------------- prep: Y = s*X + o*I, split bf16 hi/lo ---------------------
__global__ void prep_mats(const float* __restrict__ X, float s, float o) {
    unsigned gid = blockIdx.x * blockDim.x + threadIdx.x;
    float4 x = ((const float4*)X)[gid];
    unsigned within = gid & (MATSZ/4 - 1);
    int i  = (int)(within >> 6);
    int j0 = (int)(within & 63) << 2;

    float y[4];
    y[0] = s*x.x + ((i==j0+0)?o:0.f);  y[1] = s*x.y + ((i==j0+1)?o:0.f);
    y[2] = s*x.z + ((i==j0+2)?o:0.f);  y[3] = s*x.w + ((i==j0+3)?o:0.f);

    unsigned hh[4], ll[4];
    #pragma unroll
    for (int q = 0; q < 4; ++q) {
        __nv_bfloat16 h = __float2bfloat16(y[q]);
        __nv_bfloat16 l = __float2bfloat16(y[q] - __bfloat162float(h));
        hh[q] = __bfloat16_as_ushort(h);
        ll[q] = __bfloat16_as_ushort(l);
    }
    ((uint2*)g_Yh)[gid] = make_uint2(hh[0] | (hh[1]<<16), hh[2] | (hh[3]<<16));
    ((uint2*)g_Yl)[gid] = make_uint2(ll[0] | (ll[1]<<16), ll[2] | (ll[3]<<16));
    if (gid == 0) g_acc = 0.f;
}

__global__ void prep_W(const float* __restrict__ W) {
    int gid = blockIdx.x * blockDim.x + threadIdx.x;
    int c   = gid >> 16;
    int rem = gid & 65535;
    int i   = rem >> 8, j = rem & 255;
    g_Ws[gid] = 0.5f * (W[gid] + W[(c<<16) + (j<<8) + i]);
}

// ---------------- Chebyshev recurrence, column-slice resident ----------------
// CTA = (slice, b). Yhi + T-slice (hi/lo) resident in smem; A-low fragments
// loaded straight from gmem (L2-hot) -> NO barriers inside the k-loop.
// State: B smem holds T_k, tp regs hold T_{k-1}, F in regs.
__global__ void __launch_bounds__(256, 1) cheb_mma(ChebArgs args) {
    extern __shared__ char dsm[];
    const uint32_t sb = smem_u32(dsm);

    const int slice = blockIdx.x;          // 0..3
    const int b     = blockIdx.y;          // 0..127
    const int tid   = threadIdx.x;
    const int w     = tid >> 5;            // 8 warps
    const int lane  = tid & 31;
    const int laneA = lane & 15;
    const int laneHi = (lane >> 4) << 4;
    const int n0g   = slice << 6;

    const size_t moff = (size_t)b * MATSZ;
    const char* Yh = (const char*)(g_Yh + moff);
    const uint32_t* __restrict__ Ylo32 = (const uint32_t*)(g_Yl + moff);

    // ---- init: Yhi resident + B init (T1 = Y[:, slice], Y symmetric) ----
    #pragma unroll
    for (int i = 0; i < 32; ++i) {
        int op = tid + (i << 8);
        int r = op >> 5, ch = (op & 31) << 4;
        cpasync16(sb + YH_OFF + r*YROW + ch, Yh + r*512 + ch);
    }
    {
        const char* Yl = (const char*)(g_Yl + moff);
        #pragma unroll
        for (int i = 0; i < 8; ++i) {
            int op = tid + (i << 8);
            int n = op >> 5, ch = (op & 31) << 4;
            cpasync16(sb + B_HI + n*YROW + ch, Yh + (size_t)(n0g + n)*512 + ch);
            cpasync16(sb + B_LO + n*YROW + ch, Yl + (size_t)(n0g + n)*512 + ch);
        }
    }
    cp_commit();
    cp_wait<0>();
    __syncthreads();

    // ---- F, Tprev in registers (fragment layout) ----
    float F[2][8][4], tp[2][8][4];
    #pragma unroll
    for (int mt = 0; mt < 2; ++mt)
        #pragma unroll
        for (int nt = 0; nt < 8; ++nt)
            #pragma unroll
            for (int q = 0; q < 4; ++q) {
                int r  = w*32 + mt*16 + (lane >> 2) + ((q >> 1) << 3);
                int nl = nt*8 + ((lane & 3) << 1) + (q & 1);
                float yh = __bfloat162float(*(const __nv_bfloat16*)(dsm + B_HI + nl*YROW + r*2));
                float yl = __bfloat162float(*(const __nv_bfloat16*)(dsm + B_LO + nl*YROW + r*2));
                float idv = (r == n0g + nl) ? 1.f : 0.f;
                F [mt][nt][q] = args.c0*idv + args.c1*(yh + yl);
                tp[mt][nt][q] = idv;       // T0 = I
            }

    const uint32_t aAhi = sb + YH_OFF + (w*32 + laneA)*YROW + laneHi;
    const uint32_t aB   = sb + B_HI + laneA*YROW + laneHi;
    // A-low gmem fragment base (word units): row w*32+(lane>>2), word lane&3
    const uint32_t alBase = (uint32_t)((w*32 + (lane >> 2)) * 128 + (lane & 3));

    #pragma unroll 1
    for (int step = 0; step < NSTEPS; ++step) {
        const float ck = args.c[step];
        float acc[2][8][4];
        #pragma unroll
        for (int mt = 0; mt < 2; ++mt)
            #pragma unroll
            for (int nt = 0; nt < 8; ++nt)
                #pragma unroll
                for (int q = 0; q < 4; ++q) acc[mt][nt][q] = 0.f;

        // ---- barrier-free k-loop: 16 x k16 chunks ----
        #pragma unroll 4
        for (int kc = 0; kc < 16; ++kc) {
            const uint32_t kb = (uint32_t)(kc << 5);     // byte offset of k16
            const uint32_t kw = (uint32_t)(kc << 3);     // word offset

            uint32_t ah[2][4], al[2][4];
            #pragma unroll
            for (int mt = 0; mt < 2; ++mt) {
                ldsm4(ah[mt][0], ah[mt][1], ah[mt][2], ah[mt][3],
                      aAhi + (uint32_t)(mt*16*YROW) + kb);
                const uint32_t base = alBase + (uint32_t)(mt * 2048) + kw;
                al[mt][0] = __ldg(Ylo32 + base);
                al[mt][1] = __ldg(Ylo32 + base + 1024);   // row +8
                al[mt][2] = __ldg(Ylo32 + base + 4);      // k  +8
                al[mt][3] = __ldg(Ylo32 + base + 1028);
            }
            #pragma unroll
            for (int np = 0; np < 4; ++np) {
                uint32_t a = aB + (uint32_t)(np*16*YROW) + kb;
                uint32_t bh0, bh1, bh2, bh3, bl0, bl1, bl2, bl3;
                ldsm4(bh0, bh1, bh2, bh3, a);
                ldsm4(bl0, bl1, bl2, bl3, a + (uint32_t)(64*YROW));
                #pragma unroll
                for (int mt = 0; mt < 2; ++mt) {
                    mma16816(acc[mt][2*np+0], ah[mt], bh0, bh2);
                    mma16816(acc[mt][2*np+1], ah[mt], bh1, bh3);
                    mma16816(acc[mt][2*np+0], ah[mt], bl0, bl2);
                    mma16816(acc[mt][2*np+1], ah[mt], bl1, bl3);
                    mma16816(acc[mt][2*np+0], al[mt], bh0, bh2);
                    mma16816(acc[mt][2*np+1], al[mt], bh1, bh3);
                }
            }
        }
        __syncthreads();   // all B reads done before epilogue overwrites B

        // ---- epilogue: tn = 2*acc - tp ; F += ck*tn ;
        //      tp = T_k (old B value, read BEFORE overwrite) ; B = split(tn)
        #pragma unroll
        for (int mt = 0; mt < 2; ++mt)
            #pragma unroll
            for (int nt = 0; nt < 8; ++nt)
                #pragma unroll
                for (int q = 0; q < 4; ++q) {
                    int r  = w*32 + mt*16 + (lane >> 2) + ((q >> 1) << 3);
                    int nl = nt*8 + ((lane & 3) << 1) + (q & 1);
                    __nv_bfloat16* ph = (__nv_bfloat16*)(dsm + B_HI + nl*YROW + r*2);
                    __nv_bfloat16* pl = (__nv_bfloat16*)(dsm + B_LO + nl*YROW + r*2);
                    float told = __bfloat162float(*ph) + __bfloat162float(*pl);
                    float tn = 2.f*acc[mt][nt][q] - tp[mt][nt][q];
                    F [mt][nt][q] += ck * tn;
                    tp[mt][nt][q]  = told;          // T_{k-1} <- T_k
                    __nv_bfloat16 h = __float2bfloat16(tn);
                    __nv_bfloat16 l = __float2bfloat16(tn - __bfloat162float(h));
                    *ph = h;
                    *pl = l;
                }
        __syncthreads();       // B ready for next step
    }

    // ---- write F slice to gmem (once) ----
    float* Fm = g_F + moff;
    #pragma unroll
    for (int mt = 0; mt < 2; ++mt)
        #pragma unroll
        for (int nt = 0; nt < 8; ++nt)
            #pragma unroll
            for (int hrow = 0; hrow < 2; ++hrow) {
                int r  = w*32 + mt*16 + (lane >> 2) + hrow*8;
                int nl = nt*8 + ((lane & 3) << 1);
                *(float2*)(Fm + (size_t)r*256 + n0g + nl) =
                    make_float2(F[mt][nt][hrow*2], F[mt][nt][hrow*2+1]);
            }
}

// ---------------- tails ------------------------------------------------------
__global__ void center_kernel() {
    int t = blockIdx.x * blockDim.x + threadIdx.x;    // 0..65535 scalar
    float s0 = 0.f, s1 = 0.f, s2 = 0.f, s3 = 0.f;
    #pragma unroll 1
    for (int b = 0; b < BATCH; b += 4) {
        s0 += g_F[(size_t)(b+0)*MATSZ + t];
        s1 += g_F[(size_t)(b+1)*MATSZ + t];
        s2 += g_F[(size_t)(b+2)*MATSZ + t];
        s3 += g_F[(size_t)(b+3)*MATSZ + t];
    }
    g_center[t] = (s0+s1+s2+s3) * (1.f / BATCH);
}

__global__ void out_kernel(float* __restrict__ out) {
    int b = blockIdx.x;
    const float4* F4 = (const float4*)(g_F + (size_t)b*MATSZ);
    float acc[CC];
    #pragma unroll
    for (int c = 0; c < CC; ++c) acc[c] = 0.f;
    for (int t = threadIdx.x; t < MATSZ/4; t += 256) {
        float4 f = F4[t];
        #pragma unroll
        for (int c = 0; c < CC; ++c) {
            float4 w = ((const float4*)(g_Ws + (size_t)c*MATSZ))[t];
            acc[c] += f.x*w.x + f.y*w.y + f.z*w.z + f.w*w.w;
        }
    }
    __shared__ float red[8][CC];
    #pragma unroll
    for (int c = 0; c < CC; ++c) {
        float v = acc[c];
        #pragma unroll
        for (int o = 16; o; o >>= 1) v += __shfl_down_sync(0xffffffffu, v, o);
        if ((threadIdx.x & 31) == 0) red[threadIdx.x >> 5][c] = v;
    }
    __syncthreads();
    if (threadIdx.x < CC) {
        float v = 0.f;
        #pragma unroll
        for (int w = 0; w < 8; ++w) v += red[w][threadIdx.x];
        out[b*CC + threadIdx.x] = v;
    }
}

__global__ void p_kernel() {
    int c  = blockIdx.y;
    int r0 = blockIdx.x * 32;
    __shared__ float Wb[32][256];
    for (int l = 0; l < 32; ++l)
        Wb[l][threadIdx.x] = g_Ws[(size_t)c*MATSZ + (size_t)(r0+l)*256 + threadIdx.x];
    __syncthreads();
    int j = threadIdx.x;
    float acc[32];
    #pragma unroll
    for (int ii = 0; ii < 32; ++ii) acc[ii] = 0.f;
    for (int k = 0; k < 256; ++k) {
        float bv = g_center[k*256 + j];
        #pragma unroll
        for (int ii = 0; ii < 32; ++ii) acc[ii] += Wb[ii][k] * bv;
    }
    for (int ii = 0; ii < 32; ++ii)
        g_P[(size_t)c*MATSZ + (size_t)(r0+ii)*256 + j] = acc[ii];
}

__global__ void g_kernel() {
    int c = blockIdx.x;
    const float* P = g_P + (size_t)c*MATSZ;
    float acc = 0.f;
    for (int idx = threadIdx.x; idx < MATSZ; idx += 256) {
        int i = idx >> 8, j = idx & 255;
        acc += P[idx] * P[j*256 + i];
    }
    __shared__ float red[8];
    #pragma unroll
    for (int o = 16; o; o >>= 1) acc += __shfl_down_sync(0xffffffffu, acc, o);
    if ((threadIdx.x & 31) == 0) red[threadIdx.x >> 5] = acc;
    __syncthreads();
    if (threadIdx.x < 8) {
        float v = red[threadIdx.x];
        #pragma unroll
        for (int o = 4; o; o >>= 1) v += __shfl_down_sync(0xffu, v, o);
        if (threadIdx.x == 0) atomicAdd(&g_acc, v);
    }
}

__global__ void fin_kernel(float* __restrict__ out, int out_size) {
    out[out_size - 1] = g_acc * (1.f / CC);
}

// ---------------- host -------------------------------------------------------
extern "C" void kernel_launch(void* const* d_in, const int* in_sizes, int n_in,
                              void* d_out, int out_size) {
    const float* X = (const float*)d_in[0];
    const float* W = (const float*)d_in[1];
    float* out = (float*)d_out;

    const double a = 0.98, bb = 5.4;
    double coef[DEG+1];
    {
        const int N = 128;
        for (int k = 0; k <= DEG; ++k) {
            double s = 0.0;
            for (int j = 0; j < N; ++j) {
                double th  = M_PI * (j + 0.5) / N;
                double lam = 0.5*(bb+a) + 0.5*(bb-a)*cos(th);
                s += log(lam) * cos(k*th);
            }
            coef[k] = 2.0 / N * s;
        }
        coef[0] *= 0.5;
    }
    const float sc = (float)( 2.0/(bb-a));
    const float of = (float)(-(bb+a)/(bb-a));
    ChebArgs ca;
    ca.c0 = (float)coef[0];
    ca.c1 = (float)coef[1];
    for (int k = 0; k < NSTEPS; ++k) ca.c[k] = (float)coef[k+2];

    cudaFuncSetAttribute(cheb_mma, cudaFuncAttributeMaxDynamicSharedMemorySize,
                         SMEM_TOTAL);

    prep_mats<<<(BATCH*MATSZ/4)/256, 256>>>(X, sc, of);
    prep_W<<<(CC*MATSZ)/256, 256>>>(W);
    cheb_mma<<<dim3(4, BATCH), 256, SMEM_TOTAL>>>(ca);
    center_kernel<<<MATSZ/256, 256>>>();
    out_kernel<<<BATCH, 256>>>(out);
    p_kernel<<<dim3(8, CC), 256>>>();
    g_kernel<<<CC, 256>>>();
    fin_kernel<<<1, 1>>>(out, out_size);
}

// round 10
// speedup vs baseline: 5.8989x; 1.0903x over previous
#include <cuda_runtime.h>
#include <cuda_bf16.h>
#include <math.h>
#include <stdint.h>

#ifndef M_PI
#define M_PI 3.14159265358979323846
#endif

#define BATCH 128
#define HH    256
#define CC    10
#define MATSZ (HH*HH)
#define DEG   12                  /* monomial degree; PS s=4: 5 matrix mults */

// ---- smem layout (bytes). 528-stride rows -> conflict-free ldmatrix. ----
#define YROW    528
#define YH_OFF  0
#define B_HI    135168            /* 256*528 */
#define B_LO    (B_HI + 64*528)
#define SMEM_TOTAL (B_HI + 2*64*528)      /* 202752 */

// ---------------- scratch ----------------------------------------------------
__device__ __align__(16) __nv_bfloat16 g_Yh [BATCH*MATSZ];
__device__ __align__(16) __nv_bfloat16 g_Yl [BATCH*MATSZ];
__device__ __align__(16) __nv_bfloat16 g_Y2h[BATCH*MATSZ];
__device__ __align__(16) __nv_bfloat16 g_Y2l[BATCH*MATSZ];
__device__ __align__(16) __nv_bfloat16 g_Y3h[BATCH*MATSZ];
__device__ __align__(16) __nv_bfloat16 g_Y3l[BATCH*MATSZ];
__device__ __align__(16) __nv_bfloat16 g_Y4h[BATCH*MATSZ];
__device__ __align__(16) __nv_bfloat16 g_Y4l[BATCH*MATSZ];
__device__ float g_F [BATCH*MATSZ];
__device__ float g_Ws[CC*MATSZ];
__device__ float g_center[MATSZ];
__device__ float g_P [CC*MATSZ];
__device__ float g_acc;

struct HArgs { float a[DEG+1]; };

// ---------------- PTX helpers ------------------------------------------------
__device__ __forceinline__ uint32_t smem_u32(const void* p) {
    uint32_t a;
    asm("{ .reg .u64 t; cvta.to.shared.u64 t, %1; cvt.u32.u64 %0, t; }"
        : "=r"(a) : "l"(p));
    return a;
}
__device__ __forceinline__ void cpasync16(uint32_t dst, const void* src) {
    asm volatile("cp.async.cg.shared.global [%0], [%1], 16;"
                 :: "r"(dst), "l"(src) : "memory");
}
__device__ __forceinline__ void cp_commit() {
    asm volatile("cp.async.commit_group;" ::: "memory");
}
template<int N> __device__ __forceinline__ void cp_wait() {
    asm volatile("cp.async.wait_group %0;" :: "n"(N) : "memory");
}
__device__ __forceinline__ void ldsm4(uint32_t& r0, uint32_t& r1,
                                      uint32_t& r2, uint32_t& r3, uint32_t a) {
    asm volatile("ldmatrix.sync.aligned.m8n8.x4.shared.b16 {%0,%1,%2,%3}, [%4];"
                 : "=r"(r0), "=r"(r1), "=r"(r2), "=r"(r3) : "r"(a));
}
__device__ __forceinline__ void mma16816(float* c, const uint32_t* a,
                                         uint32_t b0, uint32_t b1) {
    asm volatile(
        "mma.sync.aligned.m16n8k16.row.col.f32.bf16.bf16.f32 "
        "{%0,%1,%2,%3}, {%4,%5,%6,%7}, {%8,%9}, {%0,%1,%2,%3};"
        : "+f"(c[0]), "+f"(c[1]), "+f"(c[2]), "+f"(c[3])
        : "r"(a[0]), "r"(a[1]), "r"(a[2]), "r"(a[3]), "r"(b0), "r"(b1));
}
__device__ __forceinline__ uint32_t split2(float v0, float v1, uint32_t& lo) {
    __nv_bfloat16 h0 = __float2bfloat16(v0);
    __nv_bfloat16 l0 = __float2bfloat16(v0 - __bfloat162float(h0));
    __nv_bfloat16 h1 = __float2bfloat16(v1);
    __nv_bfloat16 l1 = __float2bfloat16(v1 - __bfloat162float(h1));
    lo = (uint32_t)__bfloat16_as_ushort(l0) | ((uint32_t)__bfloat16_as_ushort(l1) << 16);
    return (uint32_t)__bfloat16_as_ushort(h0) | ((uint32_t)__bfloat16_as_ushort(h1) << 16);
}
__device__ __forceinline__ float pair_sum(uint32_t h, uint32_t l, int sel) {
    unsigned short hu = sel ? (unsigned short)(h >> 16) : (unsigned short)(h & 0xffff);
    unsigned short lu = sel ? (unsigned short)(l >> 16) : (unsigned short)(l & 0xffff);
    return __bfloat162float(__ushort_as_bfloat16(hu)) +
           __bfloat162float(__ushort_as_bfloat16(lu));
}

// ---------------- shared mult k-loop (barrier-free) --------------------------
__device__ __forceinline__ void mult_kloop(
    const char* dsm, uint32_t aAhi, uint32_t aB,
    const uint32_t* __restrict__ Alo32, uint32_t alBase,
    float (&acc)[2][8][4])
{
    #pragma unroll 4
    for (int kc = 0; kc < 16; ++kc) {
        const uint32_t kb = (uint32_t)(kc << 5);
        const uint32_t kw = (uint32_t)(kc << 3);
        uint32_t ah[2][4], al[2][4];
        #pragma unroll
        for (int mt = 0; mt < 2; ++mt) {
            ldsm4(ah[mt][0], ah[mt][1], ah[mt][2], ah[mt][3],
                  aAhi + (uint32_t)(mt*16*YROW) + kb);
            const uint32_t base = alBase + (uint32_t)(mt * 2048) + kw;
            al[mt][0] = __ldg(Alo32 + base);
            al[mt][1] = __ldg(Alo32 + base + 1024);
            al[mt][2] = __ldg(Alo32 + base + 4);
            al[mt][3] = __ldg(Alo32 + base + 1028);
        }
        #pragma unroll
        for (int np = 0; np < 4; ++np) {
            uint32_t a = aB + (uint32_t)(np*16*YROW) + kb;
            uint32_t bh0, bh1, bh2, bh3, bl0, bl1, bl2, bl3;
            ldsm4(bh0, bh1, bh2, bh3, a);
            ldsm4(bl0, bl1, bl2, bl3, a + (uint32_t)(64*YROW));
            #pragma unroll
            for (int mt = 0; mt < 2; ++mt) {
                mma16816(acc[mt][2*np+0], ah[mt], bh0, bh2);
                mma16816(acc[mt][2*np+1], ah[mt], bh1, bh3);
                mma16816(acc[mt][2*np+0], ah[mt], bl0, bl2);
                mma16816(acc[mt][2*np+1], ah[mt], bl1, bl3);
                mma16816(acc[mt][2*np+0], al[mt], bh0, bh2);
                mma16816(acc[mt][2*np+1], al[mt], bh1, bh3);
            }
        }
    }
}

// ---------------- prep: Y = s*X + o*I, split bf16 hi/lo ---------------------
__global__ void prep_mats(const float* __restrict__ X, float s, float o) {
    unsigned gid = blockIdx.x * blockDim.x + threadIdx.x;
    float4 x = ((const float4*)X)[gid];
    unsigned within = gid & (MATSZ/4 - 1);
    int i  = (int)(within >> 6);
    int j0 = (int)(within & 63) << 2;

    float y[4];
    y[0] = s*x.x + ((i==j0+0)?o:0.f);  y[1] = s*x.y + ((i==j0+1)?o:0.f);
    y[2] = s*x.z + ((i==j0+2)?o:0.f);  y[3] = s*x.w + ((i==j0+3)?o:0.f);

    unsigned hh[4], ll[4];
    #pragma unroll
    for (int q = 0; q < 4; ++q) {
        __nv_bfloat16 h = __float2bfloat16(y[q]);
        __nv_bfloat16 l = __float2bfloat16(y[q] - __bfloat162float(h));
        hh[q] = __bfloat16_as_ushort(h);
        ll[q] = __bfloat16_as_ushort(l);
    }
    ((uint2*)g_Yh)[gid] = make_uint2(hh[0] | (hh[1]<<16), hh[2] | (hh[3]<<16));
    ((uint2*)g_Yl)[gid] = make_uint2(ll[0] | (ll[1]<<16), ll[2] | (ll[3]<<16));
    if (gid == 0) g_acc = 0.f;
}

__global__ void prep_W(const float* __restrict__ W) {
    int gid = blockIdx.x * blockDim.x + threadIdx.x;
    int c   = gid >> 16;
    int rem = gid & 65535;
    int i   = rem >> 8, j = rem & 255;
    g_Ws[gid] = 0.5f * (W[gid] + W[(c<<16) + (j<<8) + i]);
}

// ---------------- pow phase: Y2 = Y*Y, Y3 = Y*Y2, Y4 = Y*Y3 ------------------
__global__ void __launch_bounds__(256, 1) pow_kernel() {
    extern __shared__ char dsm[];
    const uint32_t sb = smem_u32(dsm);

    const int slice = blockIdx.x, b = blockIdx.y;
    const int tid = threadIdx.x, w = tid >> 5, lane = tid & 31;
    const int laneA = lane & 15, laneHi = (lane >> 4) << 4;
    const int n0g = slice << 6;
    const size_t moff = (size_t)b * MATSZ;
    const char* Yh = (const char*)(g_Yh + moff);

    // A resident = Yh; C init = Y[:, slice] (Y symmetric -> rows)
    #pragma unroll
    for (int i = 0; i < 32; ++i) {
        int op = tid + (i << 8);
        int r = op >> 5, ch = (op & 31) << 4;
        cpasync16(sb + YH_OFF + r*YROW + ch, Yh + r*512 + ch);
    }
    {
        const char* Yl = (const char*)(g_Yl + moff);
        #pragma unroll
        for (int i = 0; i < 8; ++i) {
            int op = tid + (i << 8);
            int n = op >> 5, ch = (op & 31) << 4;
            cpasync16(sb + B_HI + n*YROW + ch, Yh + (size_t)(n0g + n)*512 + ch);
            cpasync16(sb + B_LO + n*YROW + ch, Yl + (size_t)(n0g + n)*512 + ch);
        }
    }
    cp_commit();
    cp_wait<0>();
    __syncthreads();

    const uint32_t aAhi = sb + YH_OFF + (w*32 + laneA)*YROW + laneHi;
    const uint32_t aB   = sb + B_HI + laneA*YROW + laneHi;
    const uint32_t alBase = (uint32_t)((w*32 + (lane >> 2)) * 128 + (lane & 3));
    const uint32_t* Alo32 = (const uint32_t*)(g_Yl + moff);

    #pragma unroll 1
    for (int step = 0; step < 3; ++step) {
        float acc[2][8][4];
        #pragma unroll
        for (int mt = 0; mt < 2; ++mt)
            #pragma unroll
            for (int nt = 0; nt < 8; ++nt)
                #pragma unroll
                for (int q = 0; q < 4; ++q) acc[mt][nt][q] = 0.f;

        mult_kloop(dsm, aAhi, aB, Alo32, alBase, acc);
        __syncthreads();

        uint32_t* gh = (uint32_t*)((step == 0 ? g_Y2h : step == 1 ? g_Y3h : g_Y4h) + moff);
        uint32_t* gl = (uint32_t*)((step == 0 ? g_Y2l : step == 1 ? g_Y3l : g_Y4l) + moff);
        const bool toSmem = (step < 2);

        #pragma unroll
        for (int mt = 0; mt < 2; ++mt)
            #pragma unroll
            for (int nt = 0; nt < 8; ++nt)
                #pragma unroll
                for (int hrow = 0; hrow < 2; ++hrow) {
                    int r  = w*32 + mt*16 + (lane >> 2) + hrow*8;
                    int c0 = nt*8 + ((lane & 3) << 1);          // local col (even)
                    float v0 = acc[mt][nt][2*hrow], v1 = acc[mt][nt][2*hrow+1];
                    uint32_t lo, hi = split2(v0, v1, lo);
                    uint32_t off = (uint32_t)(r*256 + n0g + c0);
                    gh[off >> 1] = hi;
                    gl[off >> 1] = lo;
                    if (toSmem) {
                        *(uint16_t*)(dsm + B_HI + c0*YROW + r*2)     = (uint16_t)(hi & 0xffff);
                        *(uint16_t*)(dsm + B_HI + (c0+1)*YROW + r*2) = (uint16_t)(hi >> 16);
                        *(uint16_t*)(dsm + B_LO + c0*YROW + r*2)     = (uint16_t)(lo & 0xffff);
                        *(uint16_t*)(dsm + B_LO + (c0+1)*YROW + r*2) = (uint16_t)(lo >> 16);
                    }
                }
        __syncthreads();
    }
}

// ---------------- horner phase: C0 = a12*Y4 + B2; 2 mults by Y4 --------------
__global__ void __launch_bounds__(256, 1) horner_kernel(HArgs ha) {
    extern __shared__ char dsm[];
    const uint32_t sb = smem_u32(dsm);

    const int slice = blockIdx.x, b = blockIdx.y;
    const int tid = threadIdx.x, w = tid >> 5, lane = tid & 31;
    const int laneA = lane & 15, laneHi = (lane >> 4) << 4;
    const int n0g = slice << 6;
    const size_t moff = (size_t)b * MATSZ;

    // A resident = Y4 hi
    {
        const char* A = (const char*)(g_Y4h + moff);
        #pragma unroll
        for (int i = 0; i < 32; ++i) {
            int op = tid + (i << 8);
            int r = op >> 5, ch = (op & 31) << 4;
            cpasync16(sb + YH_OFF + r*YROW + ch, A + r*512 + ch);
        }
        cp_commit();
    }

    // C init: C0 row (n0g+nl): a12*Y4 + a8*I + a9*Y + a10*Y2 + a11*Y3
    const uint32_t* Yh32  = (const uint32_t*)(g_Yh  + moff);
    const uint32_t* Yl32  = (const uint32_t*)(g_Yl  + moff);
    const uint32_t* Y2h32 = (const uint32_t*)(g_Y2h + moff);
    const uint32_t* Y2l32 = (const uint32_t*)(g_Y2l + moff);
    const uint32_t* Y3h32 = (const uint32_t*)(g_Y3h + moff);
    const uint32_t* Y3l32 = (const uint32_t*)(g_Y3l + moff);
    const uint32_t* Y4h32 = (const uint32_t*)(g_Y4h + moff);
    const uint32_t* Y4l32 = (const uint32_t*)(g_Y4l + moff);

    #pragma unroll 4
    for (int i = 0; i < 32; ++i) {
        int e  = tid + (i << 8);          // 0..8191
        int nl = e >> 7;                  // 0..63
        int k2 = (e & 127) << 1;          // even col
        int row = n0g + nl;
        uint32_t woff = (uint32_t)(row*256 + k2) >> 1;
        uint32_t yh = Yh32[woff],  yl = Yl32[woff];
        uint32_t h2 = Y2h32[woff], l2 = Y2l32[woff];
        uint32_t h3 = Y3h32[woff], l3 = Y3l32[woff];
        uint32_t h4 = Y4h32[woff], l4 = Y4l32[woff];
        float v0 = ha.a[12]*pair_sum(h4, l4, 0) + ha.a[9]*pair_sum(yh, yl, 0)
                 + ha.a[10]*pair_sum(h2, l2, 0) + ha.a[11]*pair_sum(h3, l3, 0)
                 + (row == k2   ? ha.a[8] : 0.f);
        float v1 = ha.a[12]*pair_sum(h4, l4, 1) + ha.a[9]*pair_sum(yh, yl, 1)
                 + ha.a[10]*pair_sum(h2, l2, 1) + ha.a[11]*pair_sum(h3, l3, 1)
                 + (row == k2+1 ? ha.a[8] : 0.f);
        uint32_t lo, hi = split2(v0, v1, lo);
        *(uint32_t*)(dsm + B_HI + nl*YROW + k2*2) = hi;
        *(uint32_t*)(dsm + B_LO + nl*YROW + k2*2) = lo;
    }
    cp_wait<0>();
    __syncthreads();

    const uint32_t aAhi = sb + YH_OFF + (w*32 + laneA)*YROW + laneHi;
    const uint32_t aB   = sb + B_HI + laneA*YROW + laneHi;
    const uint32_t alBase = (uint32_t)((w*32 + (lane >> 2)) * 128 + (lane & 3));
    const uint32_t* Alo32 = (const uint32_t*)(g_Y4l + moff);

    // ---- mult 1: C1 = Y4*C0 + B1 ----
    {
        float acc[2][8][4];
        #pragma unroll
        for (int mt = 0; mt < 2; ++mt)
            #pragma unroll
            for (int nt = 0; nt < 8; ++nt)
                #pragma unroll
                for (int q = 0; q < 4; ++q) acc[mt][nt][q] = 0.f;
        mult_kloop(dsm, aAhi, aB, Alo32, alBase, acc);
        __syncthreads();
        #pragma unroll
        for (int mt = 0; mt < 2; ++mt)
            #pragma unroll
            for (int nt = 0; nt < 8; ++nt)
                #pragma unroll
                for (int hrow = 0; hrow < 2; ++hrow) {
                    int r  = w*32 + mt*16 + (lane >> 2) + hrow*8;
                    int c0 = nt*8 + ((lane & 3) << 1);
                    uint32_t woff = (uint32_t)(r*256 + n0g + c0) >> 1;
                    uint32_t yh = Yh32[woff],  yl = Yl32[woff];
                    uint32_t h2 = Y2h32[woff], l2 = Y2l32[woff];
                    uint32_t h3 = Y3h32[woff], l3 = Y3l32[woff];
                    float b0 = ha.a[5]*pair_sum(yh, yl, 0) + ha.a[6]*pair_sum(h2, l2, 0)
                             + ha.a[7]*pair_sum(h3, l3, 0) + (r == n0g+c0   ? ha.a[4] : 0.f);
                    float b1 = ha.a[5]*pair_sum(yh, yl, 1) + ha.a[6]*pair_sum(h2, l2, 1)
                             + ha.a[7]*pair_sum(h3, l3, 1) + (r == n0g+c0+1 ? ha.a[4] : 0.f);
                    float v0 = acc[mt][nt][2*hrow]   + b0;
                    float v1 = acc[mt][nt][2*hrow+1] + b1;
                    uint32_t lo, hi = split2(v0, v1, lo);
                    *(uint16_t*)(dsm + B_HI + c0*YROW + r*2)     = (uint16_t)(hi & 0xffff);
                    *(uint16_t*)(dsm + B_HI + (c0+1)*YROW + r*2) = (uint16_t)(hi >> 16);
                    *(uint16_t*)(dsm + B_LO + c0*YROW + r*2)     = (uint16_t)(lo & 0xffff);
                    *(uint16_t*)(dsm + B_LO + (c0+1)*YROW + r*2) = (uint16_t)(lo >> 16);
                }
        __syncthreads();
    }

    // ---- mult 2: F = Y4*C1 + B0 (write gmem) ----
    {
        float acc[2][8][4];
        #pragma unroll
        for (int mt = 0; mt < 2; ++mt)
            #pragma unroll
            for (int nt = 0; nt < 8; ++nt)
                #pragma unroll
                for (int q = 0; q < 4; ++q) acc[mt][nt][q] = 0.f;
        mult_kloop(dsm, aAhi, aB, Alo32, alBase, acc);

        float* Fm = g_F + moff;
        #pragma unroll
        for (int mt = 0; mt < 2; ++mt)
            #pragma unroll
            for (int nt = 0; nt < 8; ++nt)
                #pragma unroll
                for (int hrow = 0; hrow < 2; ++hrow) {
                    int r  = w*32 + mt*16 + (lane >> 2) + hrow*8;
                    int c0 = nt*8 + ((lane & 3) << 1);
                    uint32_t woff = (uint32_t)(r*256 + n0g + c0) >> 1;
                    uint32_t yh = Yh32[woff],  yl = Yl32[woff];
                    uint32_t h2 = Y2h32[woff], l2 = Y2l32[woff];
                    uint32_t h3 = Y3h32[woff], l3 = Y3l32[woff];
                    float b0 = ha.a[1]*pair_sum(yh, yl, 0) + ha.a[2]*pair_sum(h2, l2, 0)
                             + ha.a[3]*pair_sum(h3, l3, 0) + (r == n0g+c0   ? ha.a[0] : 0.f);
                    float b1 = ha.a[1]*pair_sum(yh, yl, 1) + ha.a[2]*pair_sum(h2, l2, 1)
                             + ha.a[3]*pair_sum(h3, l3, 1) + (r == n0g+c0+1 ? ha.a[0] : 0.f);
                    *(float2*)(Fm + (size_t)r*256 + n0g + c0) =
                        make_float2(acc[mt][nt][2*hrow] + b0, acc[mt][nt][2*hrow+1] + b1);
                }
    }
}

// ---------------- tails ------------------------------------------------------
__global__ void center_kernel() {
    int t = blockIdx.x * blockDim.x + threadIdx.x;
    float s0 = 0.f, s1 = 0.f, s2 = 0.f, s3 = 0.f;
    #pragma unroll 1
    for (int b = 0; b < BATCH; b += 4) {
        s0 += g_F[(size_t)(b+0)*MATSZ + t];
        s1 += g_F[(size_t)(b+1)*MATSZ + t];
        s2 += g_F[(size_t)(b+2)*MATSZ + t];
        s3 += g_F[(size_t)(b+3)*MATSZ + t];
    }
    g_center[t] = (s0+s1+s2+s3) * (1.f / BATCH);
}

__global__ void out_kernel(float* __restrict__ out) {
    int b = blockIdx.x;
    const float4* F4 = (const float4*)(g_F + (size_t)b*MATSZ);
    float acc[CC];
    #pragma unroll
    for (int c = 0; c < CC; ++c) acc[c] = 0.f;
    for (int t = threadIdx.x; t < MATSZ/4; t += 256) {
        float4 f = F4[t];
        #pragma unroll
        for (int c = 0; c < CC; ++c) {
            float4 w = ((const float4*)(g_Ws + (size_t)c*MATSZ))[t];
            acc[c] += f.x*w.x + f.y*w.y + f.z*w.z + f.w*w.w;
        }
    }
    __shared__ float red[8][CC];
    #pragma unroll
    for (int c = 0; c < CC; ++c) {
        float v = acc[c];
        #pragma unroll
        for (int o = 16; o; o >>= 1) v += __shfl_down_sync(0xffffffffu, v, o);
        if ((threadIdx.x & 31) == 0) red[threadIdx.x >> 5][c] = v;
    }
    __syncthreads();
    if (threadIdx.x < CC) {
        float v = 0.f;
        #pragma unroll
        for (int w = 0; w < 8; ++w) v += red[w][threadIdx.x];
        out[b*CC + threadIdx.x] = v;
    }
}

__global__ void p_kernel() {
    int c  = blockIdx.y;
    int r0 = blockIdx.x * 32;
    __shared__ float Wb[32][256];
    for (int l = 0; l < 32; ++l)
        Wb[l][threadIdx.x] = g_Ws[(size_t)c*MATSZ + (size_t)(r0+l)*256 + threadIdx.x];
    __syncthreads();
    int j = threadIdx.x;
    float acc[32];
    #pragma unroll
    for (int ii = 0; ii < 32; ++ii) acc[ii] = 0.f;
    for (int k = 0; k < 256; ++k) {
        float bv = g_center[k*256 + j];
        #pragma unroll
        for (int ii = 0; ii < 32; ++ii) acc[ii] += Wb[ii][k] * bv;
    }
    for (int ii = 0; ii < 32; ++ii)
        g_P[(size_t)c*MATSZ + (size_t)(r0+ii)*256 + j] = acc[ii];
}

__global__ void g_kernel() {
    int c = blockIdx.x;
    const float* P = g_P + (size_t)c*MATSZ;
    float acc = 0.f;
    for (int idx = threadIdx.x; idx < MATSZ; idx += 256) {
        int i = idx >> 8, j = idx & 255;
        acc += P[idx] * P[j*256 + i];
    }
    __shared__ float red[8];
    #pragma unroll
    for (int o = 16; o; o >>= 1) acc += __shfl_down_sync(0xffffffffu, acc, o);
    if ((threadIdx.x & 31) == 0) red[threadIdx.x >> 5] = acc;
    __syncthreads();
    if (threadIdx.x < 8) {
        float v = red[threadIdx.x];
        #pragma unroll
        for (int o = 4; o; o >>= 1) v += __shfl_down_sync(0xffu, v, o);
        if (threadIdx.x == 0) atomicAdd(&g_acc, v);
    }
}

__global__ void fin_kernel(float* __restrict__ out, int out_size) {
    out[out_size - 1] = g_acc * (1.f / CC);
}

// ---------------- host -------------------------------------------------------
extern "C" void kernel_launch(void* const* d_in, const int* in_sizes, int n_in,
                              void* d_out, int out_size) {
    const float* X = (const float*)d_in[0];
    const float* W = (const float*)d_in[1];
    float* out = (float*)d_out;

    const double a = 0.98, bb = 5.4;
    double coef[DEG+1];
    {
        const int N = 128;
        for (int k = 0; k <= DEG; ++k) {
            double s = 0.0;
            for (int j = 0; j < N; ++j) {
                double th  = M_PI * (j + 0.5) / N;
                double lam = 0.5*(bb+a) + 0.5*(bb-a)*cos(th);
                s += log(lam) * cos(k*th);
            }
            coef[k] = 2.0 / N * s;
        }
        coef[0] *= 0.5;
    }
    // Chebyshev -> monomial (safe: rho = 2.375 > 2)
    double tc[DEG+1][DEG+1] = {};
    tc[0][0] = 1.0;
    tc[1][1] = 1.0;
    for (int k = 2; k <= DEG; ++k)
        for (int j = 0; j <= k; ++j)
            tc[k][j] = (j ? 2.0*tc[k-1][j-1] : 0.0) - tc[k-2][j];
    double am[DEG+1] = {};
    for (int k = 0; k <= DEG; ++k)
        for (int j = 0; j <= k; ++j)
            am[j] += coef[k] * tc[k][j];

    const float sc = (float)( 2.0/(bb-a));
    const float of = (float)(-(bb+a)/(bb-a));
    HArgs ha;
    for (int j = 0; j <= DEG; ++j) ha.a[j] = (float)am[j];

    cudaFuncSetAttribute(pow_kernel,    cudaFuncAttributeMaxDynamicSharedMemorySize, SMEM_TOTAL);
    cudaFuncSetAttribute(horner_kernel, cudaFuncAttributeMaxDynamicSharedMemorySize, SMEM_TOTAL);

    prep_mats<<<(BATCH*MATSZ/4)/256, 256>>>(X, sc, of);
    prep_W<<<(CC*MATSZ)/256, 256>>>(W);
    pow_kernel<<<dim3(4, BATCH), 256, SMEM_TOTAL>>>();
    horner_kernel<<<dim3(4, BATCH), 256, SMEM_TOTAL>>>(ha);
    center_kernel<<<MATSZ/256, 256>>>();
    out_kernel<<<BATCH, 256>>>(out);
    p_kernel<<<dim3(8, CC), 256>>>();
    g_kernel<<<CC, 256>>>();
    fin_kernel<<<1, 1>>>(out, out_size);
}